// round 1
// baseline (speedup 1.0000x reference)
#include <cuda_runtime.h>
#include <cuda_bf16.h>
#include <math.h>

// Problem constants (fixed by the dataset)
#define N_NODES 100000
#define N_EDGES 1600000
#define DIM 128
#define ODIM 64

// ---------------- scratch (static device globals; no allocation) -----------
__device__ float g_T[(size_t)N_NODES * DIM];    // GEMM output / messages source
__device__ float g_H[(size_t)N_NODES * DIM];    // node features / aggregation target
__device__ float g_C[(size_t)N_NODES * ODIM];   // final pre-softmax logits
__device__ int   g_deg[N_NODES];
__device__ float g_dinv[N_NODES];
__device__ float g_norm[N_EDGES];

// ---------------- setup kernels --------------------------------------------
__global__ void k_zero_deg(int n) {
    int i = blockIdx.x * blockDim.x + threadIdx.x;
    if (i < n) g_deg[i] = 0;
}

__global__ void k_count(const int* __restrict__ dst, int e) {
    int i = blockIdx.x * blockDim.x + threadIdx.x;
    if (i < e) atomicAdd(&g_deg[dst[i]], 1);
}

__global__ void k_dinv(int n) {
    int i = blockIdx.x * blockDim.x + threadIdx.x;
    if (i < n) {
        float d = (float)(g_deg[i] + 1);   // +1 self loop; always >= 1
        g_dinv[i] = rsqrtf(d);
    }
}

__global__ void k_norm(const int* __restrict__ src, const int* __restrict__ dst, int e) {
    int i = blockIdx.x * blockDim.x + threadIdx.x;
    if (i < e) g_norm[i] = g_dinv[src[i]] * g_dinv[dst[i]];
}

// ---------------- GEMM: C[n,BN] = act(A[n,128]) @ W[128,BN] ----------------
// act(a)[r][k] = abias ? relu(a[r][k] + abias[k]) : a[r][k]
// optional cbias added to C; optional C2[r][c] = C_raw[r][c] * dinv[r]^2
// (C2 is the self-loop init of the aggregation buffer; written only to this
//  block's own rows AFTER all its reads of A, so C2 may alias A.)
template <int BN>
__launch_bounds__(256)
__global__ void k_gemm(const float* __restrict__ A,
                       const float* __restrict__ abias,
                       const float* __restrict__ W,
                       const float* __restrict__ cbias,
                       float* __restrict__ C,
                       float* __restrict__ C2,
                       int n)
{
    constexpr int CG   = BN / 4;      // col groups (4 cols per thread)
    constexpr int RG   = 256 / CG;    // row groups (4 rows per thread)
    constexpr int ROWS = RG * 4;      // rows per block

    __shared__ float Ws[64 * BN];     // K-chunk of W
    __shared__ float Hs[ROWS * 64];   // A tile

    const int tid  = threadIdx.x;
    const int cg   = tid % CG;
    const int rg   = tid / CG;
    const int row0 = blockIdx.x * ROWS;

    float acc[4][4];
#pragma unroll
    for (int r = 0; r < 4; r++)
#pragma unroll
        for (int c = 0; c < 4; c++) acc[r][c] = 0.f;

    for (int kc = 0; kc < 128; kc += 64) {
        // load W chunk (rows kc..kc+63, all BN cols), coalesced float4
        const float4* Wg = (const float4*)(W + kc * BN);
        float4* Ws4 = (float4*)Ws;
#pragma unroll
        for (int i = tid; i < 64 * BN / 4; i += 256) Ws4[i] = Wg[i];

        // load A tile (ROWS x 64), apply fused relu(a + abias)
        float4* Hs4 = (float4*)Hs;
        for (int i = tid; i < ROWS * 16; i += 256) {
            int r  = i >> 4;            // 16 float4 per row
            int kk = (i & 15) << 2;
            int grow = row0 + r;
            float4 v = make_float4(0.f, 0.f, 0.f, 0.f);
            if (grow < n) v = *(const float4*)(A + (size_t)grow * 128 + kc + kk);
            if (abias) {
                float4 b4 = *(const float4*)(abias + kc + kk);
                v.x = fmaxf(v.x + b4.x, 0.f);
                v.y = fmaxf(v.y + b4.y, 0.f);
                v.z = fmaxf(v.z + b4.z, 0.f);
                v.w = fmaxf(v.w + b4.w, 0.f);
            }
            Hs4[i] = v;
        }
        __syncthreads();

#pragma unroll 8
        for (int k = 0; k < 64; k++) {
            float4 w4 = ((const float4*)Ws)[k * CG + cg];
#pragma unroll
            for (int r = 0; r < 4; r++) {
                float h = Hs[(rg * 4 + r) * 64 + k];
                acc[r][0] = fmaf(h, w4.x, acc[r][0]);
                acc[r][1] = fmaf(h, w4.y, acc[r][1]);
                acc[r][2] = fmaf(h, w4.z, acc[r][2]);
                acc[r][3] = fmaf(h, w4.w, acc[r][3]);
            }
        }
        __syncthreads();
    }

    // epilogue
#pragma unroll
    for (int r = 0; r < 4; r++) {
        int grow = row0 + rg * 4 + r;
        if (grow >= n) continue;
        float4 v = make_float4(acc[r][0], acc[r][1], acc[r][2], acc[r][3]);
        float4 o = v;
        if (cbias) {
            float4 b4 = *(const float4*)(cbias + cg * 4);
            o.x += b4.x; o.y += b4.y; o.z += b4.z; o.w += b4.w;
        }
        *(float4*)(C + (size_t)grow * BN + cg * 4) = o;
        if (C2) {
            float s = g_dinv[grow];
            s *= s;
            float4 u = make_float4(v.x * s, v.y * s, v.z * s, v.w * s);
            *(float4*)(C2 + (size_t)grow * BN + cg * 4) = u;
        }
    }
}

// ---------------- edge scatter: AGG[dst] += T[src] * norm[e] ---------------
__launch_bounds__(256)
__global__ void k_scatter(const float4* __restrict__ T,
                          float* __restrict__ AGG,
                          const int* __restrict__ src,
                          const int* __restrict__ dst,
                          int e)
{
    int warp  = (blockIdx.x * blockDim.x + threadIdx.x) >> 5;
    int lane  = threadIdx.x & 31;
    int nwarp = (gridDim.x * blockDim.x) >> 5;
    for (int i = warp; i < e; i += nwarp) {
        int   s  = src[i];
        int   d  = dst[i];
        float nm = g_norm[i];
        float4 v = T[(size_t)s * 32 + lane];
        v.x *= nm; v.y *= nm; v.z *= nm; v.w *= nm;
        float* p = AGG + (size_t)d * 128 + lane * 4;
        asm volatile("red.global.add.v4.f32 [%0], {%1, %2, %3, %4};"
                     :: "l"(p), "f"(v.x), "f"(v.y), "f"(v.z), "f"(v.w)
                     : "memory");
    }
}

// ---------------- log_softmax over 64 cols, one warp per row ---------------
__launch_bounds__(256)
__global__ void k_logsoftmax(const float* __restrict__ X,
                             float* __restrict__ out, int n)
{
    int warp = (blockIdx.x * blockDim.x + threadIdx.x) >> 5;
    int lane = threadIdx.x & 31;
    if (warp >= n) return;
    const float* row = X + (size_t)warp * 64;
    float v0 = row[lane];
    float v1 = row[lane + 32];
    float m = fmaxf(v0, v1);
#pragma unroll
    for (int o = 16; o > 0; o >>= 1) m = fmaxf(m, __shfl_xor_sync(0xFFFFFFFFu, m, o));
    float s = expf(v0 - m) + expf(v1 - m);
#pragma unroll
    for (int o = 16; o > 0; o >>= 1) s += __shfl_xor_sync(0xFFFFFFFFu, s, o);
    float lg = m + logf(s);
    float* orow = out + (size_t)warp * 64;
    orow[lane]      = v0 - lg;
    orow[lane + 32] = v1 - lg;
}

// ---------------- host launcher ---------------------------------------------
extern "C" void kernel_launch(void* const* d_in, const int* in_sizes, int n_in,
                              void* d_out, int out_size)
{
    const float* x   = (const float*)d_in[0];
    const int*   ei  = (const int*)d_in[1];
    const float* W0  = (const float*)d_in[2];
    const float* b0  = (const float*)d_in[3];
    const float* W1  = (const float*)d_in[4];
    const float* b1  = (const float*)d_in[5];
    const float* W2  = (const float*)d_in[6];
    const float* b2  = (const float*)d_in[7];
    const float* W3  = (const float*)d_in[8];
    const float* b3  = (const float*)d_in[9];
    const float* Wm1 = (const float*)d_in[10];
    const float* bm1 = (const float*)d_in[11];
    const float* Wm2 = (const float*)d_in[12];
    const float* bm2 = (const float*)d_in[13];
    float* out = (float*)d_out;

    const int n = in_sizes[0] / DIM;      // 100000
    const int e = in_sizes[1] / 2;        // 1600000
    const int* src = ei;
    const int* dst = ei + e;

    float *T, *H, *Cb;
    cudaGetSymbolAddress((void**)&T,  g_T);
    cudaGetSymbolAddress((void**)&H,  g_H);
    cudaGetSymbolAddress((void**)&Cb, g_C);

    // ---- setup: degrees, dinv, per-edge norm ----
    k_zero_deg<<<(n + 255) / 256, 256>>>(n);
    k_count<<<(e + 255) / 256, 256>>>(dst, e);
    k_dinv<<<(n + 255) / 256, 256>>>(n);
    k_norm<<<(e + 255) / 256, 256>>>(src, dst, e);

    const int gemm128_blocks = (n + 31) / 32;
    const int gemm64_blocks  = (n + 63) / 64;
    const int scat_blocks    = 4096;

    // ---- layer 0: T = x @ W0 ; H = T*dinv^2 ; H += scatter(T) ----
    k_gemm<128><<<gemm128_blocks, 256>>>(x, nullptr, W0, nullptr, T, H, n);
    k_scatter<<<scat_blocks, 256>>>((const float4*)T, H, src, dst, e);

    // ---- layer 1: A = relu(H + b0) (fused) ----
    k_gemm<128><<<gemm128_blocks, 256>>>(H, b0, W1, nullptr, T, H, n);
    k_scatter<<<scat_blocks, 256>>>((const float4*)T, H, src, dst, e);

    // ---- layer 2 ----
    k_gemm<128><<<gemm128_blocks, 256>>>(H, b1, W2, nullptr, T, H, n);
    k_scatter<<<scat_blocks, 256>>>((const float4*)T, H, src, dst, e);

    // ---- layer 3 ----
    k_gemm<128><<<gemm128_blocks, 256>>>(H, b2, W3, nullptr, T, H, n);
    k_scatter<<<scat_blocks, 256>>>((const float4*)T, H, src, dst, e);

    // ---- MLP head: T = relu(H + b3) @ Wm1 + bm1 ; C = T @ Wm2 + bm2 ----
    k_gemm<128><<<gemm128_blocks, 256>>>(H, b3, Wm1, bm1, T, nullptr, n);
    k_gemm<64><<<gemm64_blocks, 256>>>(T, nullptr, Wm2, bm2, Cb, nullptr, n);

    // ---- log_softmax -> out ----
    k_logsoftmax<<<(n * 32 + 255) / 256, 256>>>(Cb, out, n);
}

// round 5
// speedup vs baseline: 1.0900x; 1.0900x over previous
#include <cuda_runtime.h>
#include <cuda_bf16.h>
#include <cstdint>
#include <stdint.h>
#include <math.h>

// Problem constants (fixed by the dataset)
#define N_NODES 100000
#define N_EDGES 1600000
#define DIM 128
#define ODIM 64
#define WSLOT 16384
#define PADB 272   // smem row stride in bytes (136 bf16), multiple of 16, conflict-free

// ---------------- scratch (static device globals; no allocation) -----------
__device__ float g_T[(size_t)N_NODES * DIM];    // GEMM output / messages source
__device__ float g_H[(size_t)N_NODES * DIM];    // node features / aggregation target
__device__ float g_C[(size_t)N_NODES * ODIM];   // final pre-softmax logits
__device__ int   g_deg[N_NODES];
__device__ float g_dinv[N_NODES];
__device__ float g_norm[N_EDGES];
// transposed + bf16-split weights: 5x [128,128] + 1x [64,128], row-major [N][K]
__device__ __nv_bfloat16 g_Wh[5 * WSLOT + ODIM * DIM];
__device__ __nv_bfloat16 g_Wl[5 * WSLOT + ODIM * DIM];

// ---------------- mma.sync helper (baseline PTX, valid on compute_100) -----
__device__ __forceinline__ void mma_bf16(float* c, const unsigned int* a,
                                         const unsigned int* b) {
    asm volatile(
        "mma.sync.aligned.m16n8k16.row.col.f32.bf16.bf16.f32 "
        "{%0,%1,%2,%3}, {%4,%5,%6,%7}, {%8,%9}, {%0,%1,%2,%3};"
        : "+f"(c[0]), "+f"(c[1]), "+f"(c[2]), "+f"(c[3])
        : "r"(a[0]), "r"(a[1]), "r"(a[2]), "r"(a[3]), "r"(b[0]), "r"(b[1]));
}

// ---------------- setup kernels --------------------------------------------
__global__ void k_zero_deg(int n) {
    int i = blockIdx.x * blockDim.x + threadIdx.x;
    if (i < n) g_deg[i] = 0;
}
__global__ void k_count(const int* __restrict__ dst, int e) {
    int i = blockIdx.x * blockDim.x + threadIdx.x;
    if (i < e) atomicAdd(&g_deg[dst[i]], 1);
}
__global__ void k_dinv(int n) {
    int i = blockIdx.x * blockDim.x + threadIdx.x;
    if (i < n) g_dinv[i] = rsqrtf((float)(g_deg[i] + 1));
}
__global__ void k_norm(const int* __restrict__ src, const int* __restrict__ dst, int e) {
    int i = blockIdx.x * blockDim.x + threadIdx.x;
    if (i < e) g_norm[i] = g_dinv[src[i]] * g_dinv[dst[i]];
}

// transpose + bf16-split weights: out[n*K + k] = split(W[k*N + n])
__global__ void k_convW(const float* __restrict__ W, int K, int N,
                        __nv_bfloat16* __restrict__ oh, __nv_bfloat16* __restrict__ ol) {
    int i = blockIdx.x * blockDim.x + threadIdx.x;
    if (i >= K * N) return;
    int nrow = i / K;
    int k = i % K;
    float v = W[k * N + nrow];
    __nv_bfloat16 h = __float2bfloat16_rn(v);
    oh[i] = h;
    ol[i] = __float2bfloat16_rn(v - __bfloat162float(h));
}

// ---------------- HMMA GEMM body --------------------------------------------
// C[n,BN] = act(A[n,128]) @ W[128,BN] via split-bf16 (3 products, fp32 accum)
// act = relu(a + abias) if abias; cbias added to C; C2 = C_raw * dinv[row]^2
// Block: 128 rows x BN cols, 256 threads = 8 warps (4 row-groups x 2 col-groups)
template <int BN>
__device__ __forceinline__ void gemm_body(const float* __restrict__ A,
                                          const float* __restrict__ abias,
                                          const __nv_bfloat16* __restrict__ Wh,
                                          const __nv_bfloat16* __restrict__ Wl,
                                          const float* __restrict__ cbias,
                                          float* __restrict__ C,
                                          float* __restrict__ C2,
                                          int n, char* smem)
{
    constexpr int NT = BN / 16;            // n-tiles (8 cols each) per warp
    const unsigned int A_HI = 0;
    const unsigned int A_LO = 128 * PADB;
    const unsigned int B_HI = 2 * 128 * PADB;
    const unsigned int B_LO = B_HI + BN * PADB;

    const int tid  = threadIdx.x;
    const int wid  = tid >> 5;
    const int lane = tid & 31;
    const int wr   = wid >> 1;             // warp row group 0..3 (32 rows each)
    const int wc   = wid & 1;              // warp col group 0..1 (NT*8 cols each)
    const int row0 = blockIdx.x * 128;

    // ---- convert A tile (128 x 128 f32 -> bf16 hi/lo), fused relu(+abias)
    for (int i = tid; i < 128 * 16; i += 256) {
        int row = i >> 4;
        int unit = i & 15;
        int grow = row0 + row;
        float4 a0 = make_float4(0.f, 0.f, 0.f, 0.f);
        float4 a1 = a0;
        if (grow < n) {
            const float4* p = (const float4*)(A + (size_t)grow * 128 + unit * 8);
            a0 = p[0]; a1 = p[1];
        }
        if (abias) {
            const float4* b = (const float4*)(abias + unit * 8);
            float4 b0 = b[0], b1 = b[1];
            a0.x = fmaxf(a0.x + b0.x, 0.f); a0.y = fmaxf(a0.y + b0.y, 0.f);
            a0.z = fmaxf(a0.z + b0.z, 0.f); a0.w = fmaxf(a0.w + b0.w, 0.f);
            a1.x = fmaxf(a1.x + b1.x, 0.f); a1.y = fmaxf(a1.y + b1.y, 0.f);
            a1.z = fmaxf(a1.z + b1.z, 0.f); a1.w = fmaxf(a1.w + b1.w, 0.f);
        }
        float v[8];
        v[0] = a0.x; v[1] = a0.y; v[2] = a0.z; v[3] = a0.w;
        v[4] = a1.x; v[5] = a1.y; v[6] = a1.z; v[7] = a1.w;
        unsigned int hi[4], lo[4];
#pragma unroll
        for (int j = 0; j < 4; j++) {
            __nv_bfloat16 h0 = __float2bfloat16_rn(v[2 * j]);
            __nv_bfloat16 h1 = __float2bfloat16_rn(v[2 * j + 1]);
            float r0 = v[2 * j] - __bfloat162float(h0);
            float r1 = v[2 * j + 1] - __bfloat162float(h1);
            __nv_bfloat16 l0 = __float2bfloat16_rn(r0);
            __nv_bfloat16 l1 = __float2bfloat16_rn(r1);
            hi[j] = ((unsigned int)__bfloat16_as_ushort(h1) << 16) | __bfloat16_as_ushort(h0);
            lo[j] = ((unsigned int)__bfloat16_as_ushort(l1) << 16) | __bfloat16_as_ushort(l0);
        }
        unsigned int off = (unsigned int)row * PADB + (unsigned int)unit * 16;
        *(uint4*)(smem + A_HI + off) = make_uint4(hi[0], hi[1], hi[2], hi[3]);
        *(uint4*)(smem + A_LO + off) = make_uint4(lo[0], lo[1], lo[2], lo[3]);
    }

    // ---- load W tiles (BN rows x 128 bf16 each, pre-split in global [N][K])
    for (int i = tid; i < BN * 16; i += 256) {
        int row = i >> 4;
        int unit = i & 15;
        unsigned int off = (unsigned int)row * PADB + (unsigned int)unit * 16;
        *(uint4*)(smem + B_HI + off) = ((const uint4*)Wh)[row * 16 + unit];
        *(uint4*)(smem + B_LO + off) = ((const uint4*)Wl)[row * 16 + unit];
    }
    __syncthreads();

    // ---- mainloop: 8 k-steps of m16n8k16, 3 products each
    const int g  = lane >> 2;              // 0..7
    const int tg = lane & 3;               // 0..3
    float acc[2][NT][4];
#pragma unroll
    for (int mt = 0; mt < 2; mt++)
#pragma unroll
        for (int nt = 0; nt < NT; nt++)
#pragma unroll
            for (int j = 0; j < 4; j++) acc[mt][nt][j] = 0.f;

#pragma unroll
    for (int ks = 0; ks < 8; ks++) {
        const unsigned int kb = (unsigned int)(ks * 16 + tg * 2) * 2;  // byte off in row
        unsigned int ah[2][4], al[2][4];
#pragma unroll
        for (int mt = 0; mt < 2; mt++) {
            unsigned int ro = (unsigned int)(wr * 32 + mt * 16 + g) * PADB + kb;
            ah[mt][0] = *(const unsigned int*)(smem + A_HI + ro);
            ah[mt][1] = *(const unsigned int*)(smem + A_HI + ro + 8 * PADB);
            ah[mt][2] = *(const unsigned int*)(smem + A_HI + ro + 16);
            ah[mt][3] = *(const unsigned int*)(smem + A_HI + ro + 8 * PADB + 16);
            al[mt][0] = *(const unsigned int*)(smem + A_LO + ro);
            al[mt][1] = *(const unsigned int*)(smem + A_LO + ro + 8 * PADB);
            al[mt][2] = *(const unsigned int*)(smem + A_LO + ro + 16);
            al[mt][3] = *(const unsigned int*)(smem + A_LO + ro + 8 * PADB + 16);
        }
#pragma unroll
        for (int nt = 0; nt < NT; nt++) {
            unsigned int no = (unsigned int)(wc * NT * 8 + nt * 8 + g) * PADB + kb;
            unsigned int bh[2], bl[2];
            bh[0] = *(const unsigned int*)(smem + B_HI + no);
            bh[1] = *(const unsigned int*)(smem + B_HI + no + 16);
            bl[0] = *(const unsigned int*)(smem + B_LO + no);
            bl[1] = *(const unsigned int*)(smem + B_LO + no + 16);
#pragma unroll
            for (int mt = 0; mt < 2; mt++) {
                mma_bf16(acc[mt][nt], ah[mt], bh);
                mma_bf16(acc[mt][nt], ah[mt], bl);
                mma_bf16(acc[mt][nt], al[mt], bh);
            }
        }
    }

    // ---- epilogue
#pragma unroll
    for (int mt = 0; mt < 2; mt++) {
        int r0i = row0 + wr * 32 + mt * 16 + g;        // rows r0i and r0i+8
        float s0 = 0.f, s1 = 0.f;
        if (C2) {
            if (r0i < n)     { s0 = g_dinv[r0i];     s0 *= s0; }
            if (r0i + 8 < n) { s1 = g_dinv[r0i + 8]; s1 *= s1; }
        }
#pragma unroll
        for (int nt = 0; nt < NT; nt++) {
            int col = wc * NT * 8 + nt * 8 + tg * 2;
            float c0 = acc[mt][nt][0], c1 = acc[mt][nt][1];
            float c2 = acc[mt][nt][2], c3 = acc[mt][nt][3];
            float o0 = c0, o1 = c1, o2 = c2, o3 = c3;
            if (cbias) {
                float b0 = cbias[col], b1 = cbias[col + 1];
                o0 += b0; o1 += b1; o2 += b0; o3 += b1;
            }
            if (r0i < n) {
                *(float2*)(C + (size_t)r0i * BN + col) = make_float2(o0, o1);
                if (C2) *(float2*)(C2 + (size_t)r0i * BN + col) = make_float2(c0 * s0, c1 * s0);
            }
            if (r0i + 8 < n) {
                *(float2*)(C + (size_t)(r0i + 8) * BN + col) = make_float2(o2, o3);
                if (C2) *(float2*)(C2 + (size_t)(r0i + 8) * BN + col) = make_float2(c2 * s1, c3 * s1);
            }
        }
    }
}

__global__ void __launch_bounds__(256, 1)
k_gemm128(const float* A, const float* abias,
          const __nv_bfloat16* Wh, const __nv_bfloat16* Wl,
          const float* cbias, float* C, float* C2, int n)
{
    extern __shared__ __align__(16) char smem_dyn[];
    gemm_body<128>(A, abias, Wh, Wl, cbias, C, C2, n, smem_dyn);
}

__global__ void __launch_bounds__(256, 1)
k_gemm64(const float* A, const float* abias,
         const __nv_bfloat16* Wh, const __nv_bfloat16* Wl,
         const float* cbias, float* C, float* C2, int n)
{
    extern __shared__ __align__(16) char smem_dyn[];
    gemm_body<64>(A, abias, Wh, Wl, cbias, C, C2, n, smem_dyn);
}

// ---------------- edge scatter: AGG[dst] += T[src] * norm[e] ---------------
__launch_bounds__(256)
__global__ void k_scatter(const float4* __restrict__ T,
                          float* __restrict__ AGG,
                          const int* __restrict__ src,
                          const int* __restrict__ dst,
                          int e)
{
    int warp  = (blockIdx.x * blockDim.x + threadIdx.x) >> 5;
    int lane  = threadIdx.x & 31;
    int nwarp = (gridDim.x * blockDim.x) >> 5;
    for (int i = warp; i < e; i += nwarp) {
        int   s  = src[i];
        int   d  = dst[i];
        float nm = g_norm[i];
        float4 v = T[(size_t)s * 32 + lane];
        v.x *= nm; v.y *= nm; v.z *= nm; v.w *= nm;
        float* p = AGG + (size_t)d * 128 + lane * 4;
        asm volatile("red.global.add.v4.f32 [%0], {%1, %2, %3, %4};"
                     :: "l"(p), "f"(v.x), "f"(v.y), "f"(v.z), "f"(v.w)
                     : "memory");
    }
}

// ---------------- log_softmax over 64 cols, one warp per row ---------------
__launch_bounds__(256)
__global__ void k_logsoftmax(const float* __restrict__ X,
                             float* __restrict__ out, int n)
{
    int warp = (blockIdx.x * blockDim.x + threadIdx.x) >> 5;
    int lane = threadIdx.x & 31;
    if (warp >= n) return;
    const float* row = X + (size_t)warp * 64;
    float v0 = row[lane];
    float v1 = row[lane + 32];
    float m = fmaxf(v0, v1);
#pragma unroll
    for (int o = 16; o > 0; o >>= 1) m = fmaxf(m, __shfl_xor_sync(0xFFFFFFFFu, m, o));
    float s = expf(v0 - m) + expf(v1 - m);
#pragma unroll
    for (int o = 16; o > 0; o >>= 1) s += __shfl_xor_sync(0xFFFFFFFFu, s, o);
    float lg = m + logf(s);
    float* orow = out + (size_t)warp * 64;
    orow[lane]      = v0 - lg;
    orow[lane + 32] = v1 - lg;
}

// ---------------- host launcher ---------------------------------------------
extern "C" void kernel_launch(void* const* d_in, const int* in_sizes, int n_in,
                              void* d_out, int out_size)
{
    const float* x   = (const float*)d_in[0];
    const int*   ei  = (const int*)d_in[1];
    const float* W0  = (const float*)d_in[2];
    const float* b0  = (const float*)d_in[3];
    const float* W1  = (const float*)d_in[4];
    const float* b1  = (const float*)d_in[5];
    const float* W2  = (const float*)d_in[6];
    const float* b2  = (const float*)d_in[7];
    const float* W3  = (const float*)d_in[8];
    const float* b3  = (const float*)d_in[9];
    const float* Wm1 = (const float*)d_in[10];
    const float* bm1 = (const float*)d_in[11];
    const float* Wm2 = (const float*)d_in[12];
    const float* bm2 = (const float*)d_in[13];
    float* out = (float*)d_out;

    const int n = in_sizes[0] / DIM;      // 100000
    const int e = in_sizes[1] / 2;        // 1600000
    const int* src = ei;
    const int* dst = ei + e;

    float* T = 0;
    float* H = 0;
    float* Cb = 0;
    __nv_bfloat16* Wh = 0;
    __nv_bfloat16* Wl = 0;
    cudaGetSymbolAddress((void**)&T,  g_T);
    cudaGetSymbolAddress((void**)&H,  g_H);
    cudaGetSymbolAddress((void**)&Cb, g_C);
    cudaGetSymbolAddress((void**)&Wh, g_Wh);
    cudaGetSymbolAddress((void**)&Wl, g_Wl);

    // dynamic smem: A(hi+lo) 128 rows + B(hi+lo) BN rows, PADB bytes per row
    const int SM128 = 2 * 128 * PADB + 2 * 128 * PADB;   // 139264
    const int SM64  = 2 * 128 * PADB + 2 * 64  * PADB;   // 104448
    cudaFuncSetAttribute(k_gemm128, cudaFuncAttributeMaxDynamicSharedMemorySize, SM128);
    cudaFuncSetAttribute(k_gemm64,  cudaFuncAttributeMaxDynamicSharedMemorySize, SM64);

    // ---- setup: degrees, dinv, per-edge norm, weight transpose+split ----
    k_zero_deg<<<(n + 255) / 256, 256>>>(n);
    k_count<<<(e + 255) / 256, 256>>>(dst, e);
    k_dinv<<<(n + 255) / 256, 256>>>(n);
    k_norm<<<(e + 255) / 256, 256>>>(src, dst, e);

    k_convW<<<64, 256>>>(W0,  128, 128, Wh + 0 * WSLOT, Wl + 0 * WSLOT);
    k_convW<<<64, 256>>>(W1,  128, 128, Wh + 1 * WSLOT, Wl + 1 * WSLOT);
    k_convW<<<64, 256>>>(W2,  128, 128, Wh + 2 * WSLOT, Wl + 2 * WSLOT);
    k_convW<<<64, 256>>>(W3,  128, 128, Wh + 3 * WSLOT, Wl + 3 * WSLOT);
    k_convW<<<64, 256>>>(Wm1, 128, 128, Wh + 4 * WSLOT, Wl + 4 * WSLOT);
    k_convW<<<32, 256>>>(Wm2, 128, 64,  Wh + 5 * WSLOT, Wl + 5 * WSLOT);

    const int gblocks = (n + 127) / 128;   // 782
    const int scat_blocks = 4096;

    // ---- layer 0: T = x @ W0 ; H = T*dinv^2 ; H += scatter(T) ----
    k_gemm128<<<gblocks, 256, SM128>>>(x, 0, Wh + 0 * WSLOT, Wl + 0 * WSLOT, 0, T, H, n);
    k_scatter<<<scat_blocks, 256>>>((const float4*)T, H, src, dst, e);

    // ---- layer 1 ----
    k_gemm128<<<gblocks, 256, SM128>>>(H, b0, Wh + 1 * WSLOT, Wl + 1 * WSLOT, 0, T, H, n);
    k_scatter<<<scat_blocks, 256>>>((const float4*)T, H, src, dst, e);

    // ---- layer 2 ----
    k_gemm128<<<gblocks, 256, SM128>>>(H, b1, Wh + 2 * WSLOT, Wl + 2 * WSLOT, 0, T, H, n);
    k_scatter<<<scat_blocks, 256>>>((const float4*)T, H, src, dst, e);

    // ---- layer 3 ----
    k_gemm128<<<gblocks, 256, SM128>>>(H, b2, Wh + 3 * WSLOT, Wl + 3 * WSLOT, 0, T, H, n);
    k_scatter<<<scat_blocks, 256>>>((const float4*)T, H, src, dst, e);

    // ---- MLP head ----
    k_gemm128<<<gblocks, 256, SM128>>>(H, b3, Wh + 4 * WSLOT, Wl + 4 * WSLOT, bm1, T, 0, n);
    k_gemm64<<<gblocks, 256, SM64>>>(T, 0, Wh + 5 * WSLOT, Wl + 5 * WSLOT, bm2, Cb, 0, n);

    // ---- log_softmax -> out ----
    k_logsoftmax<<<(n * 32 + 255) / 256, 256>>>(Cb, out, n);
}

// round 6
// speedup vs baseline: 1.6695x; 1.5317x over previous
#include <cuda_runtime.h>
#include <cuda_bf16.h>
#include <cstdint>
#include <stdint.h>
#include <math.h>

// Problem constants (fixed by the dataset)
#define N_NODES 100000
#define N_EDGES 1600000
#define DIM 128
#define ODIM 64
#define WSLOT 16384
#define PADB 272   // smem row stride in bytes (136 bf16), multiple of 16, conflict-free
#define SCHUNK 1024
#define NSCANB ((N_NODES + SCHUNK - 1) / SCHUNK)   // 98

// ---------------- scratch (static device globals; no allocation) -----------
__device__ float g_T[(size_t)N_NODES * DIM];    // GEMM output (pre-scaled by dinv)
__device__ float g_H[(size_t)N_NODES * DIM];    // node features / aggregation target
__device__ float g_C[(size_t)N_NODES * ODIM];   // final pre-softmax logits
__device__ int   g_deg[N_NODES];
__device__ int   g_cur[N_NODES];
__device__ int   g_off[N_NODES + 1];
__device__ int   g_csr[N_EDGES];
__device__ int   g_bsum[128];
__device__ float g_dinv[N_NODES];
// transposed + bf16-split weights: 5x [128,128] + 1x [64,128], row-major [N][K]
__device__ __nv_bfloat16 g_Wh[5 * WSLOT + ODIM * DIM];
__device__ __nv_bfloat16 g_Wl[5 * WSLOT + ODIM * DIM];

// ---------------- mma.sync helper (baseline PTX, valid on compute_100) -----
__device__ __forceinline__ void mma_bf16(float* c, const unsigned int* a,
                                         const unsigned int* b) {
    asm volatile(
        "mma.sync.aligned.m16n8k16.row.col.f32.bf16.bf16.f32 "
        "{%0,%1,%2,%3}, {%4,%5,%6,%7}, {%8,%9}, {%0,%1,%2,%3};"
        : "+f"(c[0]), "+f"(c[1]), "+f"(c[2]), "+f"(c[3])
        : "r"(a[0]), "r"(a[1]), "r"(a[2]), "r"(a[3]), "r"(b[0]), "r"(b[1]));
}

// ---------------- setup kernels --------------------------------------------
__global__ void k_zero(int n) {
    int i = blockIdx.x * blockDim.x + threadIdx.x;
    if (i < n) { g_deg[i] = 0; g_cur[i] = 0; }
}
__global__ void k_count(const int* __restrict__ dst, int e) {
    int i = blockIdx.x * blockDim.x + threadIdx.x;
    if (i < e) atomicAdd(&g_deg[dst[i]], 1);
}
__global__ void k_dinv(int n) {
    int i = blockIdx.x * blockDim.x + threadIdx.x;
    if (i < n) g_dinv[i] = rsqrtf((float)(g_deg[i] + 1));
}

// ---- exclusive scan of g_deg into g_off (3-kernel classic) ----
__global__ void k_bsum(int n) {            // grid NSCANB, block 1024
    __shared__ int sh[SCHUNK];
    int i = blockIdx.x * SCHUNK + threadIdx.x;
    sh[threadIdx.x] = (i < n) ? g_deg[i] : 0;
    __syncthreads();
    for (int off = SCHUNK / 2; off > 0; off >>= 1) {
        if (threadIdx.x < off) sh[threadIdx.x] += sh[threadIdx.x + off];
        __syncthreads();
    }
    if (threadIdx.x == 0) g_bsum[blockIdx.x] = sh[0];
}
__global__ void k_bscan(int nb) {          // 1 block, 128 threads
    __shared__ int sh[128];
    int v = (threadIdx.x < nb) ? g_bsum[threadIdx.x] : 0;
    sh[threadIdx.x] = v;
    __syncthreads();
    for (int off = 1; off < 128; off <<= 1) {
        int t = (threadIdx.x >= off) ? sh[threadIdx.x - off] : 0;
        __syncthreads();
        sh[threadIdx.x] += t;
        __syncthreads();
    }
    if (threadIdx.x < nb) g_bsum[threadIdx.x] = sh[threadIdx.x] - v;  // exclusive
}
__global__ void k_offsets(int n) {         // grid NSCANB, block 1024
    __shared__ int sh[SCHUNK];
    int i = blockIdx.x * SCHUNK + threadIdx.x;
    int v = (i < n) ? g_deg[i] : 0;
    sh[threadIdx.x] = v;
    __syncthreads();
    for (int off = 1; off < SCHUNK; off <<= 1) {
        int t = (threadIdx.x >= off) ? sh[threadIdx.x - off] : 0;
        __syncthreads();
        sh[threadIdx.x] += t;
        __syncthreads();
    }
    int excl = g_bsum[blockIdx.x] + sh[threadIdx.x] - v;
    if (i < n) g_off[i] = excl;
    if (i == n - 1) g_off[n] = excl + v;
}
__global__ void k_fill(const int* __restrict__ src, const int* __restrict__ dst, int e) {
    int i = blockIdx.x * blockDim.x + threadIdx.x;
    if (i < e) {
        int d = dst[i];
        int pos = g_off[d] + atomicAdd(&g_cur[d], 1);
        g_csr[pos] = src[i];
    }
}

// transpose + bf16-split weights: out[n*K + k] = split(W[k*N + n])
__global__ void k_convW(const float* __restrict__ W, int K, int N,
                        __nv_bfloat16* __restrict__ oh, __nv_bfloat16* __restrict__ ol) {
    int i = blockIdx.x * blockDim.x + threadIdx.x;
    if (i >= K * N) return;
    int nrow = i / K;
    int k = i % K;
    float v = W[k * N + nrow];
    __nv_bfloat16 h = __float2bfloat16_rn(v);
    oh[i] = h;
    ol[i] = __float2bfloat16_rn(v - __bfloat162float(h));
}

// ---------------- HMMA GEMM body --------------------------------------------
// C[n,BN] = act(A[n,128]) @ W[128,BN] via split-bf16 (3 products, fp32 accum)
// act = relu(a + abias) if abias. Epilogue: if doScale, C = acc*dinv[row]
// (no bias); else C = acc + cbias (if cbias).
template <int BN>
__device__ __forceinline__ void gemm_body(const float* __restrict__ A,
                                          const float* __restrict__ abias,
                                          const __nv_bfloat16* __restrict__ Wh,
                                          const __nv_bfloat16* __restrict__ Wl,
                                          const float* __restrict__ cbias,
                                          float* __restrict__ C,
                                          int doScale,
                                          int n, char* smem)
{
    constexpr int NT = BN / 16;            // n-tiles (8 cols each) per warp
    const unsigned int A_HI = 0;
    const unsigned int A_LO = 128 * PADB;
    const unsigned int B_HI = 2 * 128 * PADB;
    const unsigned int B_LO = B_HI + BN * PADB;

    const int tid  = threadIdx.x;
    const int wid  = tid >> 5;
    const int lane = tid & 31;
    const int wr   = wid >> 1;             // warp row group 0..3 (32 rows each)
    const int wc   = wid & 1;              // warp col group 0..1 (NT*8 cols each)
    const int row0 = blockIdx.x * 128;

    // ---- convert A tile (128 x 128 f32 -> bf16 hi/lo), fused relu(+abias)
    for (int i = tid; i < 128 * 16; i += 256) {
        int row = i >> 4;
        int unit = i & 15;
        int grow = row0 + row;
        float4 a0 = make_float4(0.f, 0.f, 0.f, 0.f);
        float4 a1 = a0;
        if (grow < n) {
            const float4* p = (const float4*)(A + (size_t)grow * 128 + unit * 8);
            a0 = p[0]; a1 = p[1];
        }
        if (abias) {
            const float4* b = (const float4*)(abias + unit * 8);
            float4 b0 = b[0], b1 = b[1];
            a0.x = fmaxf(a0.x + b0.x, 0.f); a0.y = fmaxf(a0.y + b0.y, 0.f);
            a0.z = fmaxf(a0.z + b0.z, 0.f); a0.w = fmaxf(a0.w + b0.w, 0.f);
            a1.x = fmaxf(a1.x + b1.x, 0.f); a1.y = fmaxf(a1.y + b1.y, 0.f);
            a1.z = fmaxf(a1.z + b1.z, 0.f); a1.w = fmaxf(a1.w + b1.w, 0.f);
        }
        float v[8];
        v[0] = a0.x; v[1] = a0.y; v[2] = a0.z; v[3] = a0.w;
        v[4] = a1.x; v[5] = a1.y; v[6] = a1.z; v[7] = a1.w;
        unsigned int hi[4], lo[4];
#pragma unroll
        for (int j = 0; j < 4; j++) {
            __nv_bfloat16 h0 = __float2bfloat16_rn(v[2 * j]);
            __nv_bfloat16 h1 = __float2bfloat16_rn(v[2 * j + 1]);
            float r0 = v[2 * j] - __bfloat162float(h0);
            float r1 = v[2 * j + 1] - __bfloat162float(h1);
            __nv_bfloat16 l0 = __float2bfloat16_rn(r0);
            __nv_bfloat16 l1 = __float2bfloat16_rn(r1);
            hi[j] = ((unsigned int)__bfloat16_as_ushort(h1) << 16) | __bfloat16_as_ushort(h0);
            lo[j] = ((unsigned int)__bfloat16_as_ushort(l1) << 16) | __bfloat16_as_ushort(l0);
        }
        unsigned int off = (unsigned int)row * PADB + (unsigned int)unit * 16;
        *(uint4*)(smem + A_HI + off) = make_uint4(hi[0], hi[1], hi[2], hi[3]);
        *(uint4*)(smem + A_LO + off) = make_uint4(lo[0], lo[1], lo[2], lo[3]);
    }

    // ---- load W tiles (BN rows x 128 bf16 each, pre-split in global [N][K])
    for (int i = tid; i < BN * 16; i += 256) {
        int row = i >> 4;
        int unit = i & 15;
        unsigned int off = (unsigned int)row * PADB + (unsigned int)unit * 16;
        *(uint4*)(smem + B_HI + off) = ((const uint4*)Wh)[row * 16 + unit];
        *(uint4*)(smem + B_LO + off) = ((const uint4*)Wl)[row * 16 + unit];
    }
    __syncthreads();

    // ---- mainloop: 8 k-steps of m16n8k16, 3 products each
    const int g  = lane >> 2;              // 0..7
    const int tg = lane & 3;               // 0..3
    float acc[2][NT][4];
#pragma unroll
    for (int mt = 0; mt < 2; mt++)
#pragma unroll
        for (int nt = 0; nt < NT; nt++)
#pragma unroll
            for (int j = 0; j < 4; j++) acc[mt][nt][j] = 0.f;

#pragma unroll
    for (int ks = 0; ks < 8; ks++) {
        const unsigned int kb = (unsigned int)(ks * 16 + tg * 2) * 2;  // byte off in row
        unsigned int ah[2][4], al[2][4];
#pragma unroll
        for (int mt = 0; mt < 2; mt++) {
            unsigned int ro = (unsigned int)(wr * 32 + mt * 16 + g) * PADB + kb;
            ah[mt][0] = *(const unsigned int*)(smem + A_HI + ro);
            ah[mt][1] = *(const unsigned int*)(smem + A_HI + ro + 8 * PADB);
            ah[mt][2] = *(const unsigned int*)(smem + A_HI + ro + 16);
            ah[mt][3] = *(const unsigned int*)(smem + A_HI + ro + 8 * PADB + 16);
            al[mt][0] = *(const unsigned int*)(smem + A_LO + ro);
            al[mt][1] = *(const unsigned int*)(smem + A_LO + ro + 8 * PADB);
            al[mt][2] = *(const unsigned int*)(smem + A_LO + ro + 16);
            al[mt][3] = *(const unsigned int*)(smem + A_LO + ro + 8 * PADB + 16);
        }
#pragma unroll
        for (int nt = 0; nt < NT; nt++) {
            unsigned int no = (unsigned int)(wc * NT * 8 + nt * 8 + g) * PADB + kb;
            unsigned int bh[2], bl[2];
            bh[0] = *(const unsigned int*)(smem + B_HI + no);
            bh[1] = *(const unsigned int*)(smem + B_HI + no + 16);
            bl[0] = *(const unsigned int*)(smem + B_LO + no);
            bl[1] = *(const unsigned int*)(smem + B_LO + no + 16);
#pragma unroll
            for (int mt = 0; mt < 2; mt++) {
                mma_bf16(acc[mt][nt], ah[mt], bh);
                mma_bf16(acc[mt][nt], ah[mt], bl);
                mma_bf16(acc[mt][nt], al[mt], bh);
            }
        }
    }

    // ---- epilogue
#pragma unroll
    for (int mt = 0; mt < 2; mt++) {
        int r0i = row0 + wr * 32 + mt * 16 + g;        // rows r0i and r0i+8
        float s0 = 1.f, s1 = 1.f;
        if (doScale) {
            if (r0i < n)     s0 = g_dinv[r0i];
            if (r0i + 8 < n) s1 = g_dinv[r0i + 8];
        }
#pragma unroll
        for (int nt = 0; nt < NT; nt++) {
            int col = wc * NT * 8 + nt * 8 + tg * 2;
            float c0 = acc[mt][nt][0], c1 = acc[mt][nt][1];
            float c2 = acc[mt][nt][2], c3 = acc[mt][nt][3];
            if (doScale) {
                c0 *= s0; c1 *= s0; c2 *= s1; c3 *= s1;
            } else if (cbias) {
                float b0 = cbias[col], b1 = cbias[col + 1];
                c0 += b0; c1 += b1; c2 += b0; c3 += b1;
            }
            if (r0i < n)
                *(float2*)(C + (size_t)r0i * BN + col) = make_float2(c0, c1);
            if (r0i + 8 < n)
                *(float2*)(C + (size_t)(r0i + 8) * BN + col) = make_float2(c2, c3);
        }
    }
}

__global__ void __launch_bounds__(256, 1)
k_gemm128(const float* A, const float* abias,
          const __nv_bfloat16* Wh, const __nv_bfloat16* Wl,
          const float* cbias, float* C, int doScale, int n)
{
    extern __shared__ __align__(16) char smem_dyn[];
    gemm_body<128>(A, abias, Wh, Wl, cbias, C, doScale, n, smem_dyn);
}

__global__ void __launch_bounds__(256, 1)
k_gemm64(const float* A, const float* abias,
         const __nv_bfloat16* Wh, const __nv_bfloat16* Wl,
         const float* cbias, float* C, int doScale, int n)
{
    extern __shared__ __align__(16) char smem_dyn[];
    gemm_body<64>(A, abias, Wh, Wl, cbias, C, doScale, n, smem_dyn);
}

// ---------------- CSR pull-gather: H[d] = dinv[d]*(Ts[d] + sum Ts[src]) ----
__launch_bounds__(256)
__global__ void k_gather(const float4* __restrict__ Ts,
                         float4* __restrict__ H, int n)
{
    int warp = (blockIdx.x * blockDim.x + threadIdx.x) >> 5;
    int lane = threadIdx.x & 31;
    if (warp >= n) return;
    int beg = g_off[warp];
    int end = g_off[warp + 1];

    float4 acc = Ts[(size_t)warp * 32 + lane];   // self loop (dinv applied below)

    for (int base = beg; base < end; base += 32) {
        int nrem = end - base;
        int cnt = nrem < 32 ? nrem : 32;
        int idx = (lane < cnt) ? g_csr[base + lane] : 0;
        int j = 0;
        for (; j + 4 <= cnt; j += 4) {
            int s0 = __shfl_sync(0xFFFFFFFFu, idx, j);
            int s1 = __shfl_sync(0xFFFFFFFFu, idx, j + 1);
            int s2 = __shfl_sync(0xFFFFFFFFu, idx, j + 2);
            int s3 = __shfl_sync(0xFFFFFFFFu, idx, j + 3);
            float4 v0 = Ts[(size_t)s0 * 32 + lane];
            float4 v1 = Ts[(size_t)s1 * 32 + lane];
            float4 v2 = Ts[(size_t)s2 * 32 + lane];
            float4 v3 = Ts[(size_t)s3 * 32 + lane];
            acc.x += v0.x; acc.y += v0.y; acc.z += v0.z; acc.w += v0.w;
            acc.x += v1.x; acc.y += v1.y; acc.z += v1.z; acc.w += v1.w;
            acc.x += v2.x; acc.y += v2.y; acc.z += v2.z; acc.w += v2.w;
            acc.x += v3.x; acc.y += v3.y; acc.z += v3.z; acc.w += v3.w;
        }
        for (; j < cnt; j++) {
            int s = __shfl_sync(0xFFFFFFFFu, idx, j);
            float4 v = Ts[(size_t)s * 32 + lane];
            acc.x += v.x; acc.y += v.y; acc.z += v.z; acc.w += v.w;
        }
    }

    float di = g_dinv[warp];
    acc.x *= di; acc.y *= di; acc.z *= di; acc.w *= di;
    H[(size_t)warp * 32 + lane] = acc;
}

// ---------------- log_softmax over 64 cols, one warp per row ---------------
__launch_bounds__(256)
__global__ void k_logsoftmax(const float* __restrict__ X,
                             float* __restrict__ out, int n)
{
    int warp = (blockIdx.x * blockDim.x + threadIdx.x) >> 5;
    int lane = threadIdx.x & 31;
    if (warp >= n) return;
    const float* row = X + (size_t)warp * 64;
    float v0 = row[lane];
    float v1 = row[lane + 32];
    float m = fmaxf(v0, v1);
#pragma unroll
    for (int o = 16; o > 0; o >>= 1) m = fmaxf(m, __shfl_xor_sync(0xFFFFFFFFu, m, o));
    float s = expf(v0 - m) + expf(v1 - m);
#pragma unroll
    for (int o = 16; o > 0; o >>= 1) s += __shfl_xor_sync(0xFFFFFFFFu, s, o);
    float lg = m + logf(s);
    float* orow = out + (size_t)warp * 64;
    orow[lane]      = v0 - lg;
    orow[lane + 32] = v1 - lg;
}

// ---------------- host launcher ---------------------------------------------
extern "C" void kernel_launch(void* const* d_in, const int* in_sizes, int n_in,
                              void* d_out, int out_size)
{
    const float* x   = (const float*)d_in[0];
    const int*   ei  = (const int*)d_in[1];
    const float* W0  = (const float*)d_in[2];
    const float* b0  = (const float*)d_in[3];
    const float* W1  = (const float*)d_in[4];
    const float* b1  = (const float*)d_in[5];
    const float* W2  = (const float*)d_in[6];
    const float* b2  = (const float*)d_in[7];
    const float* W3  = (const float*)d_in[8];
    const float* b3  = (const float*)d_in[9];
    const float* Wm1 = (const float*)d_in[10];
    const float* bm1 = (const float*)d_in[11];
    const float* Wm2 = (const float*)d_in[12];
    const float* bm2 = (const float*)d_in[13];
    float* out = (float*)d_out;

    const int n = in_sizes[0] / DIM;      // 100000
    const int e = in_sizes[1] / 2;        // 1600000
    const int* src = ei;
    const int* dst = ei + e;

    float* T = 0;
    float* H = 0;
    float* Cb = 0;
    __nv_bfloat16* Wh = 0;
    __nv_bfloat16* Wl = 0;
    cudaGetSymbolAddress((void**)&T,  g_T);
    cudaGetSymbolAddress((void**)&H,  g_H);
    cudaGetSymbolAddress((void**)&Cb, g_C);
    cudaGetSymbolAddress((void**)&Wh, g_Wh);
    cudaGetSymbolAddress((void**)&Wl, g_Wl);

    // dynamic smem: A(hi+lo) 128 rows + B(hi+lo) BN rows, PADB bytes per row
    const int SM128 = 2 * 128 * PADB + 2 * 128 * PADB;   // 139264
    const int SM64  = 2 * 128 * PADB + 2 * 64  * PADB;   // 104448
    cudaFuncSetAttribute(k_gemm128, cudaFuncAttributeMaxDynamicSharedMemorySize, SM128);
    cudaFuncSetAttribute(k_gemm64,  cudaFuncAttributeMaxDynamicSharedMemorySize, SM64);

    const int nscanb = (n + SCHUNK - 1) / SCHUNK;

    // ---- setup: degrees, dinv, CSR (offsets + fill), weight split ----
    k_zero<<<(n + 255) / 256, 256>>>(n);
    k_count<<<(e + 255) / 256, 256>>>(dst, e);
    k_dinv<<<(n + 255) / 256, 256>>>(n);
    k_bsum<<<nscanb, SCHUNK>>>(n);
    k_bscan<<<1, 128>>>(nscanb);
    k_offsets<<<nscanb, SCHUNK>>>(n);
    k_fill<<<(e + 255) / 256, 256>>>(src, dst, e);

    k_convW<<<64, 256>>>(W0,  128, 128, Wh + 0 * WSLOT, Wl + 0 * WSLOT);
    k_convW<<<64, 256>>>(W1,  128, 128, Wh + 1 * WSLOT, Wl + 1 * WSLOT);
    k_convW<<<64, 256>>>(W2,  128, 128, Wh + 2 * WSLOT, Wl + 2 * WSLOT);
    k_convW<<<64, 256>>>(W3,  128, 128, Wh + 3 * WSLOT, Wl + 3 * WSLOT);
    k_convW<<<64, 256>>>(Wm1, 128, 128, Wh + 4 * WSLOT, Wl + 4 * WSLOT);
    k_convW<<<32, 256>>>(Wm2, 128, 64,  Wh + 5 * WSLOT, Wl + 5 * WSLOT);

    const int gblocks = (n + 127) / 128;                 // 782
    const int gatherb = (n * 32 + 255) / 256;            // 12500

    // ---- 4 GCN layers: Ts = act(H)@W * dinv ; H = gather(Ts) ----
    k_gemm128<<<gblocks, 256, SM128>>>(x, 0, Wh + 0 * WSLOT, Wl + 0 * WSLOT, 0, T, 1, n);
    k_gather<<<gatherb, 256>>>((const float4*)T, (float4*)H, n);

    k_gemm128<<<gblocks, 256, SM128>>>(H, b0, Wh + 1 * WSLOT, Wl + 1 * WSLOT, 0, T, 1, n);
    k_gather<<<gatherb, 256>>>((const float4*)T, (float4*)H, n);

    k_gemm128<<<gblocks, 256, SM128>>>(H, b1, Wh + 2 * WSLOT, Wl + 2 * WSLOT, 0, T, 1, n);
    k_gather<<<gatherb, 256>>>((const float4*)T, (float4*)H, n);

    k_gemm128<<<gblocks, 256, SM128>>>(H, b2, Wh + 3 * WSLOT, Wl + 3 * WSLOT, 0, T, 1, n);
    k_gather<<<gatherb, 256>>>((const float4*)T, (float4*)H, n);

    // ---- MLP head ----
    k_gemm128<<<gblocks, 256, SM128>>>(H, b3, Wh + 4 * WSLOT, Wl + 4 * WSLOT, bm1, T, 0, n);
    k_gemm64<<<gblocks, 256, SM64>>>(T, 0, Wh + 5 * WSLOT, Wl + 5 * WSLOT, bm2, Cb, 0, n);

    // ---- log_softmax -> out ----
    k_logsoftmax<<<(n * 32 + 255) / 256, 256>>>(Cb, out, n);
}

// round 7
// speedup vs baseline: 1.9616x; 1.1750x over previous
#include <cuda_runtime.h>
#include <cuda_bf16.h>
#include <cuda_fp16.h>
#include <cstdint>
#include <stdint.h>
#include <math.h>

// Problem constants (fixed by the dataset)
#define N_NODES 100000
#define N_EDGES 1600000
#define DIM 128
#define ODIM 64
#define WSLOT 16384
#define WTOT (5 * WSLOT + ODIM * DIM)
#define PADB 272   // smem row stride in bytes (136 bf16), multiple of 16, conflict-free
#define SCHUNK 1024

// ---------------- scratch (static device globals; no allocation) -----------
__device__ float  g_T[(size_t)N_NODES * DIM];   // fp32 GEMM output (MLP head)
__device__ __half g_T16[(size_t)N_NODES * DIM]; // fp16 messages (GCN layers)
__device__ float  g_H[(size_t)N_NODES * DIM];   // node features / agg target
__device__ float  g_C[(size_t)N_NODES * ODIM];  // final pre-softmax logits
__device__ int    g_deg[N_NODES];
__device__ int    g_cur[N_NODES];
__device__ int    g_off[N_NODES + 1];
__device__ int    g_csr[N_EDGES];
__device__ int    g_bsum[128];
__device__ float  g_dinv[N_NODES];
// transposed + bf16-split weights: 5x [128,128] + 1x [64,128], row-major [N][K]
__device__ __nv_bfloat16 g_Wh[WTOT];
__device__ __nv_bfloat16 g_Wl[WTOT];

// ---------------- mma.sync helper (baseline PTX, valid on compute_100) -----
__device__ __forceinline__ void mma_bf16(float* c, const unsigned int* a,
                                         const unsigned int* b) {
    asm volatile(
        "mma.sync.aligned.m16n8k16.row.col.f32.bf16.bf16.f32 "
        "{%0,%1,%2,%3}, {%4,%5,%6,%7}, {%8,%9}, {%0,%1,%2,%3};"
        : "+f"(c[0]), "+f"(c[1]), "+f"(c[2]), "+f"(c[3])
        : "r"(a[0]), "r"(a[1]), "r"(a[2]), "r"(a[3]), "r"(b[0]), "r"(b[1]));
}

// ---------------- setup kernels --------------------------------------------
__global__ void k_zero(int n) {
    int i = blockIdx.x * blockDim.x + threadIdx.x;
    if (i < n) { g_deg[i] = 0; g_cur[i] = 0; }
}
__global__ void k_count(const int* __restrict__ dst, int e) {
    int i = blockIdx.x * blockDim.x + threadIdx.x;
    if (i < e) atomicAdd(&g_deg[dst[i]], 1);
}
__global__ void k_dinv(int n) {
    int i = blockIdx.x * blockDim.x + threadIdx.x;
    if (i < n) g_dinv[i] = rsqrtf((float)(g_deg[i] + 1));
}

// ---- exclusive scan of g_deg into g_off (3-kernel classic) ----
__global__ void k_bsum(int n) {            // grid NSCANB, block 1024
    __shared__ int sh[SCHUNK];
    int i = blockIdx.x * SCHUNK + threadIdx.x;
    sh[threadIdx.x] = (i < n) ? g_deg[i] : 0;
    __syncthreads();
    for (int off = SCHUNK / 2; off > 0; off >>= 1) {
        if (threadIdx.x < off) sh[threadIdx.x] += sh[threadIdx.x + off];
        __syncthreads();
    }
    if (threadIdx.x == 0) g_bsum[blockIdx.x] = sh[0];
}
__global__ void k_bscan(int nb) {          // 1 block, 128 threads
    __shared__ int sh[128];
    int v = (threadIdx.x < nb) ? g_bsum[threadIdx.x] : 0;
    sh[threadIdx.x] = v;
    __syncthreads();
    for (int off = 1; off < 128; off <<= 1) {
        int t = (threadIdx.x >= off) ? sh[threadIdx.x - off] : 0;
        __syncthreads();
        sh[threadIdx.x] += t;
        __syncthreads();
    }
    if (threadIdx.x < nb) g_bsum[threadIdx.x] = sh[threadIdx.x] - v;  // exclusive
}
__global__ void k_offsets(int n) {         // grid NSCANB, block 1024
    __shared__ int sh[SCHUNK];
    int i = blockIdx.x * SCHUNK + threadIdx.x;
    int v = (i < n) ? g_deg[i] : 0;
    sh[threadIdx.x] = v;
    __syncthreads();
    for (int off = 1; off < SCHUNK; off <<= 1) {
        int t = (threadIdx.x >= off) ? sh[threadIdx.x - off] : 0;
        __syncthreads();
        sh[threadIdx.x] += t;
        __syncthreads();
    }
    int excl = g_bsum[blockIdx.x] + sh[threadIdx.x] - v;
    if (i < n) g_off[i] = excl;
    if (i == n - 1) g_off[n] = excl + v;
}
__global__ void k_fill(const int* __restrict__ src, const int* __restrict__ dst, int e) {
    int i = blockIdx.x * blockDim.x + threadIdx.x;
    if (i < e) {
        int d = dst[i];
        int pos = g_off[d] + atomicAdd(&g_cur[d], 1);
        g_csr[pos] = src[i];
    }
}

// transpose + bf16-split ALL weights in one launch: slot = i / WSLOT
__global__ void k_convW_all(const float* __restrict__ W0, const float* __restrict__ W1,
                            const float* __restrict__ W2, const float* __restrict__ W3,
                            const float* __restrict__ Wm1, const float* __restrict__ Wm2) {
    int i = blockIdx.x * blockDim.x + threadIdx.x;
    if (i >= WTOT) return;
    int slot = i >> 14;          // / 16384
    int j = i & 16383;
    const float* W;
    int N;
    switch (slot) {
        case 0:  W = W0;  N = 128; break;
        case 1:  W = W1;  N = 128; break;
        case 2:  W = W2;  N = 128; break;
        case 3:  W = W3;  N = 128; break;
        case 4:  W = Wm1; N = 128; break;
        default: W = Wm2; N = 64;  break;
    }
    const int K = 128;
    int nrow = j / K;
    int k = j % K;
    float v = W[k * N + nrow];
    __nv_bfloat16 h = __float2bfloat16_rn(v);
    g_Wh[i] = h;
    g_Wl[i] = __float2bfloat16_rn(v - __bfloat162float(h));
}

// ---------------- HMMA GEMM body --------------------------------------------
// via split-bf16 (3 products, fp32 accum); act = relu(a + abias) if abias.
// If C16 != 0:  C16[row] = half(acc * dinv[row])           (GCN layer mode)
// else:         C[row]  = acc + cbias (if cbias)           (MLP mode)
template <int BN>
__device__ __forceinline__ void gemm_body(const float* __restrict__ A,
                                          const float* __restrict__ abias,
                                          const __nv_bfloat16* __restrict__ Wh,
                                          const __nv_bfloat16* __restrict__ Wl,
                                          const float* __restrict__ cbias,
                                          float* __restrict__ C,
                                          __half* __restrict__ C16,
                                          int n, char* smem)
{
    constexpr int NT = BN / 16;            // n-tiles (8 cols each) per warp
    const unsigned int A_HI = 0;
    const unsigned int A_LO = 128 * PADB;
    const unsigned int B_HI = 2 * 128 * PADB;
    const unsigned int B_LO = B_HI + BN * PADB;

    const int tid  = threadIdx.x;
    const int wid  = tid >> 5;
    const int lane = tid & 31;
    const int wr   = wid >> 1;             // warp row group 0..3 (32 rows each)
    const int wc   = wid & 1;              // warp col group 0..1 (NT*8 cols each)
    const int row0 = blockIdx.x * 128;

    // ---- convert A tile (128 x 128 f32 -> bf16 hi/lo), fused relu(+abias)
    for (int i = tid; i < 128 * 16; i += 256) {
        int row = i >> 4;
        int unit = i & 15;
        int grow = row0 + row;
        float4 a0 = make_float4(0.f, 0.f, 0.f, 0.f);
        float4 a1 = a0;
        if (grow < n) {
            const float4* p = (const float4*)(A + (size_t)grow * 128 + unit * 8);
            a0 = p[0]; a1 = p[1];
        }
        if (abias) {
            const float4* b = (const float4*)(abias + unit * 8);
            float4 b0 = b[0], b1 = b[1];
            a0.x = fmaxf(a0.x + b0.x, 0.f); a0.y = fmaxf(a0.y + b0.y, 0.f);
            a0.z = fmaxf(a0.z + b0.z, 0.f); a0.w = fmaxf(a0.w + b0.w, 0.f);
            a1.x = fmaxf(a1.x + b1.x, 0.f); a1.y = fmaxf(a1.y + b1.y, 0.f);
            a1.z = fmaxf(a1.z + b1.z, 0.f); a1.w = fmaxf(a1.w + b1.w, 0.f);
        }
        float v[8];
        v[0] = a0.x; v[1] = a0.y; v[2] = a0.z; v[3] = a0.w;
        v[4] = a1.x; v[5] = a1.y; v[6] = a1.z; v[7] = a1.w;
        unsigned int hi[4], lo[4];
#pragma unroll
        for (int j = 0; j < 4; j++) {
            __nv_bfloat16 h0 = __float2bfloat16_rn(v[2 * j]);
            __nv_bfloat16 h1 = __float2bfloat16_rn(v[2 * j + 1]);
            float r0 = v[2 * j] - __bfloat162float(h0);
            float r1 = v[2 * j + 1] - __bfloat162float(h1);
            __nv_bfloat16 l0 = __float2bfloat16_rn(r0);
            __nv_bfloat16 l1 = __float2bfloat16_rn(r1);
            hi[j] = ((unsigned int)__bfloat16_as_ushort(h1) << 16) | __bfloat16_as_ushort(h0);
            lo[j] = ((unsigned int)__bfloat16_as_ushort(l1) << 16) | __bfloat16_as_ushort(l0);
        }
        unsigned int off = (unsigned int)row * PADB + (unsigned int)unit * 16;
        *(uint4*)(smem + A_HI + off) = make_uint4(hi[0], hi[1], hi[2], hi[3]);
        *(uint4*)(smem + A_LO + off) = make_uint4(lo[0], lo[1], lo[2], lo[3]);
    }

    // ---- load W tiles (BN rows x 128 bf16 each, pre-split in global [N][K])
    for (int i = tid; i < BN * 16; i += 256) {
        int row = i >> 4;
        int unit = i & 15;
        unsigned int off = (unsigned int)row * PADB + (unsigned int)unit * 16;
        *(uint4*)(smem + B_HI + off) = ((const uint4*)Wh)[row * 16 + unit];
        *(uint4*)(smem + B_LO + off) = ((const uint4*)Wl)[row * 16 + unit];
    }
    __syncthreads();

    // ---- mainloop: 8 k-steps of m16n8k16, 3 products each
    const int g  = lane >> 2;              // 0..7
    const int tg = lane & 3;               // 0..3
    float acc[2][NT][4];
#pragma unroll
    for (int mt = 0; mt < 2; mt++)
#pragma unroll
        for (int nt = 0; nt < NT; nt++)
#pragma unroll
            for (int j = 0; j < 4; j++) acc[mt][nt][j] = 0.f;

#pragma unroll
    for (int ks = 0; ks < 8; ks++) {
        const unsigned int kb = (unsigned int)(ks * 16 + tg * 2) * 2;  // byte off in row
        unsigned int ah[2][4], al[2][4];
#pragma unroll
        for (int mt = 0; mt < 2; mt++) {
            unsigned int ro = (unsigned int)(wr * 32 + mt * 16 + g) * PADB + kb;
            ah[mt][0] = *(const unsigned int*)(smem + A_HI + ro);
            ah[mt][1] = *(const unsigned int*)(smem + A_HI + ro + 8 * PADB);
            ah[mt][2] = *(const unsigned int*)(smem + A_HI + ro + 16);
            ah[mt][3] = *(const unsigned int*)(smem + A_HI + ro + 8 * PADB + 16);
            al[mt][0] = *(const unsigned int*)(smem + A_LO + ro);
            al[mt][1] = *(const unsigned int*)(smem + A_LO + ro + 8 * PADB);
            al[mt][2] = *(const unsigned int*)(smem + A_LO + ro + 16);
            al[mt][3] = *(const unsigned int*)(smem + A_LO + ro + 8 * PADB + 16);
        }
#pragma unroll
        for (int nt = 0; nt < NT; nt++) {
            unsigned int no = (unsigned int)(wc * NT * 8 + nt * 8 + g) * PADB + kb;
            unsigned int bh[2], bl[2];
            bh[0] = *(const unsigned int*)(smem + B_HI + no);
            bh[1] = *(const unsigned int*)(smem + B_HI + no + 16);
            bl[0] = *(const unsigned int*)(smem + B_LO + no);
            bl[1] = *(const unsigned int*)(smem + B_LO + no + 16);
#pragma unroll
            for (int mt = 0; mt < 2; mt++) {
                mma_bf16(acc[mt][nt], ah[mt], bh);
                mma_bf16(acc[mt][nt], ah[mt], bl);
                mma_bf16(acc[mt][nt], al[mt], bh);
            }
        }
    }

    // ---- epilogue
#pragma unroll
    for (int mt = 0; mt < 2; mt++) {
        int r0i = row0 + wr * 32 + mt * 16 + g;        // rows r0i and r0i+8
        float s0 = 1.f, s1 = 1.f;
        if (C16) {
            if (r0i < n)     s0 = g_dinv[r0i];
            if (r0i + 8 < n) s1 = g_dinv[r0i + 8];
        }
#pragma unroll
        for (int nt = 0; nt < NT; nt++) {
            int col = wc * NT * 8 + nt * 8 + tg * 2;
            float c0 = acc[mt][nt][0], c1 = acc[mt][nt][1];
            float c2 = acc[mt][nt][2], c3 = acc[mt][nt][3];
            if (C16) {
                if (r0i < n)
                    *(__half2*)(C16 + (size_t)r0i * BN + col) =
                        __floats2half2_rn(c0 * s0, c1 * s0);
                if (r0i + 8 < n)
                    *(__half2*)(C16 + (size_t)(r0i + 8) * BN + col) =
                        __floats2half2_rn(c2 * s1, c3 * s1);
            } else {
                if (cbias) {
                    float b0 = cbias[col], b1 = cbias[col + 1];
                    c0 += b0; c1 += b1; c2 += b0; c3 += b1;
                }
                if (r0i < n)
                    *(float2*)(C + (size_t)r0i * BN + col) = make_float2(c0, c1);
                if (r0i + 8 < n)
                    *(float2*)(C + (size_t)(r0i + 8) * BN + col) = make_float2(c2, c3);
            }
        }
    }
}

__global__ void __launch_bounds__(256, 1)
k_gemm128(const float* A, const float* abias,
          const __nv_bfloat16* Wh, const __nv_bfloat16* Wl,
          const float* cbias, float* C, __half* C16, int n)
{
    extern __shared__ __align__(16) char smem_dyn[];
    gemm_body<128>(A, abias, Wh, Wl, cbias, C, C16, n, smem_dyn);
}

__global__ void __launch_bounds__(256, 1)
k_gemm64(const float* A, const float* abias,
         const __nv_bfloat16* Wh, const __nv_bfloat16* Wl,
         const float* cbias, float* C, __half* C16, int n)
{
    extern __shared__ __align__(16) char smem_dyn[];
    gemm_body<64>(A, abias, Wh, Wl, cbias, C, C16, n, smem_dyn);
}

// ---------------- CSR pull-gather (fp16 messages, fp32 accum) --------------
// H[d] = dinv[d] * (T16[d] + sum_{s in N(d)} T16[s])
__device__ __forceinline__ float4 h4_to_f4(uint2 v) {
    __half2 a = *reinterpret_cast<__half2*>(&v.x);
    __half2 b = *reinterpret_cast<__half2*>(&v.y);
    float2 fa = __half22float2(a);
    float2 fb = __half22float2(b);
    return make_float4(fa.x, fa.y, fb.x, fb.y);
}

__launch_bounds__(256)
__global__ void k_gather(const uint2* __restrict__ T16,
                         float4* __restrict__ H, int n)
{
    int warp = (blockIdx.x * blockDim.x + threadIdx.x) >> 5;
    int lane = threadIdx.x & 31;
    if (warp >= n) return;
    int beg = g_off[warp];
    int end = g_off[warp + 1];

    float4 acc = h4_to_f4(T16[(size_t)warp * 32 + lane]);   // self loop

    for (int base = beg; base < end; base += 32) {
        int nrem = end - base;
        int cnt = nrem < 32 ? nrem : 32;
        int idx = (lane < cnt) ? g_csr[base + lane] : 0;
        int j = 0;
        for (; j + 4 <= cnt; j += 4) {
            int s0 = __shfl_sync(0xFFFFFFFFu, idx, j);
            int s1 = __shfl_sync(0xFFFFFFFFu, idx, j + 1);
            int s2 = __shfl_sync(0xFFFFFFFFu, idx, j + 2);
            int s3 = __shfl_sync(0xFFFFFFFFu, idx, j + 3);
            float4 v0 = h4_to_f4(T16[(size_t)s0 * 32 + lane]);
            float4 v1 = h4_to_f4(T16[(size_t)s1 * 32 + lane]);
            float4 v2 = h4_to_f4(T16[(size_t)s2 * 32 + lane]);
            float4 v3 = h4_to_f4(T16[(size_t)s3 * 32 + lane]);
            acc.x += v0.x; acc.y += v0.y; acc.z += v0.z; acc.w += v0.w;
            acc.x += v1.x; acc.y += v1.y; acc.z += v1.z; acc.w += v1.w;
            acc.x += v2.x; acc.y += v2.y; acc.z += v2.z; acc.w += v2.w;
            acc.x += v3.x; acc.y += v3.y; acc.z += v3.z; acc.w += v3.w;
        }
        for (; j < cnt; j++) {
            int s = __shfl_sync(0xFFFFFFFFu, idx, j);
            float4 v = h4_to_f4(T16[(size_t)s * 32 + lane]);
            acc.x += v.x; acc.y += v.y; acc.z += v.z; acc.w += v.w;
        }
    }

    float di = g_dinv[warp];
    acc.x *= di; acc.y *= di; acc.z *= di; acc.w *= di;
    H[(size_t)warp * 32 + lane] = acc;
}

// ---------------- log_softmax over 64 cols, one warp per row ---------------
__launch_bounds__(256)
__global__ void k_logsoftmax(const float* __restrict__ X,
                             float* __restrict__ out, int n)
{
    int warp = (blockIdx.x * blockDim.x + threadIdx.x) >> 5;
    int lane = threadIdx.x & 31;
    if (warp >= n) return;
    const float* row = X + (size_t)warp * 64;
    float v0 = row[lane];
    float v1 = row[lane + 32];
    float m = fmaxf(v0, v1);
#pragma unroll
    for (int o = 16; o > 0; o >>= 1) m = fmaxf(m, __shfl_xor_sync(0xFFFFFFFFu, m, o));
    float s = expf(v0 - m) + expf(v1 - m);
#pragma unroll
    for (int o = 16; o > 0; o >>= 1) s += __shfl_xor_sync(0xFFFFFFFFu, s, o);
    float lg = m + logf(s);
    float* orow = out + (size_t)warp * 64;
    orow[lane]      = v0 - lg;
    orow[lane + 32] = v1 - lg;
}

// ---------------- host launcher ---------------------------------------------
extern "C" void kernel_launch(void* const* d_in, const int* in_sizes, int n_in,
                              void* d_out, int out_size)
{
    const float* x   = (const float*)d_in[0];
    const int*   ei  = (const int*)d_in[1];
    const float* W0  = (const float*)d_in[2];
    const float* b0  = (const float*)d_in[3];
    const float* W1  = (const float*)d_in[4];
    const float* b1  = (const float*)d_in[5];
    const float* W2  = (const float*)d_in[6];
    const float* b2  = (const float*)d_in[7];
    const float* W3  = (const float*)d_in[8];
    const float* b3  = (const float*)d_in[9];
    const float* Wm1 = (const float*)d_in[10];
    const float* bm1 = (const float*)d_in[11];
    const float* Wm2 = (const float*)d_in[12];
    const float* bm2 = (const float*)d_in[13];
    float* out = (float*)d_out;

    const int n = in_sizes[0] / DIM;      // 100000
    const int e = in_sizes[1] / 2;        // 1600000
    const int* src = ei;
    const int* dst = ei + e;

    float* T = 0;
    __half* T16 = 0;
    float* H = 0;
    float* Cb = 0;
    __nv_bfloat16* Wh = 0;
    __nv_bfloat16* Wl = 0;
    cudaGetSymbolAddress((void**)&T,   g_T);
    cudaGetSymbolAddress((void**)&T16, g_T16);
    cudaGetSymbolAddress((void**)&H,   g_H);
    cudaGetSymbolAddress((void**)&Cb,  g_C);
    cudaGetSymbolAddress((void**)&Wh,  g_Wh);
    cudaGetSymbolAddress((void**)&Wl,  g_Wl);

    // dynamic smem: A(hi+lo) 128 rows + B(hi+lo) BN rows, PADB bytes per row
    const int SM128 = 2 * 128 * PADB + 2 * 128 * PADB;   // 139264
    const int SM64  = 2 * 128 * PADB + 2 * 64  * PADB;   // 104448
    cudaFuncSetAttribute(k_gemm128, cudaFuncAttributeMaxDynamicSharedMemorySize, SM128);
    cudaFuncSetAttribute(k_gemm64,  cudaFuncAttributeMaxDynamicSharedMemorySize, SM64);

    const int nscanb = (n + SCHUNK - 1) / SCHUNK;

    // ---- setup: degrees, dinv, CSR (offsets + fill), weight split ----
    k_zero<<<(n + 255) / 256, 256>>>(n);
    k_count<<<(e + 255) / 256, 256>>>(dst, e);
    k_dinv<<<(n + 255) / 256, 256>>>(n);
    k_bsum<<<nscanb, SCHUNK>>>(n);
    k_bscan<<<1, 128>>>(nscanb);
    k_offsets<<<nscanb, SCHUNK>>>(n);
    k_fill<<<(e + 255) / 256, 256>>>(src, dst, e);
    k_convW_all<<<(WTOT + 255) / 256, 256>>>(W0, W1, W2, W3, Wm1, Wm2);

    const int gblocks = (n + 127) / 128;                 // 782
    const int gatherb = (n * 32 + 255) / 256;            // 12500

    // ---- 4 GCN layers: T16 = (act(H)@W) * dinv (fp16) ; H = gather(T16) ----
    k_gemm128<<<gblocks, 256, SM128>>>(x, 0, Wh + 0 * WSLOT, Wl + 0 * WSLOT, 0, 0, T16, n);
    k_gather<<<gatherb, 256>>>((const uint2*)T16, (float4*)H, n);

    k_gemm128<<<gblocks, 256, SM128>>>(H, b0, Wh + 1 * WSLOT, Wl + 1 * WSLOT, 0, 0, T16, n);
    k_gather<<<gatherb, 256>>>((const uint2*)T16, (float4*)H, n);

    k_gemm128<<<gblocks, 256, SM128>>>(H, b1, Wh + 2 * WSLOT, Wl + 2 * WSLOT, 0, 0, T16, n);
    k_gather<<<gatherb, 256>>>((const uint2*)T16, (float4*)H, n);

    k_gemm128<<<gblocks, 256, SM128>>>(H, b2, Wh + 3 * WSLOT, Wl + 3 * WSLOT, 0, 0, T16, n);
    k_gather<<<gatherb, 256>>>((const uint2*)T16, (float4*)H, n);

    // ---- MLP head (fp32 path) ----
    k_gemm128<<<gblocks, 256, SM128>>>(H, b3, Wh + 4 * WSLOT, Wl + 4 * WSLOT, bm1, T, 0, n);
    k_gemm64<<<gblocks, 256, SM64>>>(T, 0, Wh + 5 * WSLOT, Wl + 5 * WSLOT, bm2, Cb, 0, n);

    // ---- log_softmax -> out ----
    k_logsoftmax<<<(n * 32 + 255) / 256, 256>>>(Cb, out, n);
}

// round 8
// speedup vs baseline: 2.0481x; 1.0441x over previous
#include <cuda_runtime.h>
#include <cuda_bf16.h>
#include <cuda_fp16.h>
#include <cstdint>
#include <stdint.h>
#include <math.h>

// Problem constants (fixed by the dataset)
#define N_NODES 100000
#define N_EDGES 1600000
#define DIM 128
#define ODIM 64
#define WSLOT 16384
#define WTOT (5 * WSLOT + ODIM * DIM)
#define PADB 272   // smem row stride in bytes (136 bf16), multiple of 16, conflict-free
#define SCHUNK 1024

// ---------------- scratch (static device globals; no allocation) -----------
__device__ float  g_T[(size_t)N_NODES * DIM];   // fp32 GEMM output (MLP head)
__device__ __half g_T16[(size_t)N_NODES * DIM]; // fp16 messages (GCN layers)
__device__ __half g_H16[(size_t)N_NODES * DIM]; // fp16 aggregated features
__device__ float  g_C[(size_t)N_NODES * ODIM];  // final pre-softmax logits
__device__ int    g_deg[N_NODES];
__device__ int    g_cur[N_NODES];
__device__ int    g_off[N_NODES + 1];
__device__ int    g_csr[N_EDGES];
__device__ int    g_bsum[128];
__device__ float  g_dinv[N_NODES];
// transposed + bf16-split weights: 5x [128,128] + 1x [64,128], row-major [N][K]
__device__ __nv_bfloat16 g_Wh[WTOT];
__device__ __nv_bfloat16 g_Wl[WTOT];

// ---------------- mma.sync helper (baseline PTX, valid on compute_100) -----
__device__ __forceinline__ void mma_bf16(float* c, const unsigned int* a,
                                         const unsigned int* b) {
    asm volatile(
        "mma.sync.aligned.m16n8k16.row.col.f32.bf16.bf16.f32 "
        "{%0,%1,%2,%3}, {%4,%5,%6,%7}, {%8,%9}, {%0,%1,%2,%3};"
        : "+f"(c[0]), "+f"(c[1]), "+f"(c[2]), "+f"(c[3])
        : "r"(a[0]), "r"(a[1]), "r"(a[2]), "r"(a[3]), "r"(b[0]), "r"(b[1]));
}

// ---------------- setup kernels --------------------------------------------
__global__ void k_zero(int n) {
    int i = blockIdx.x * blockDim.x + threadIdx.x;
    if (i < n) { g_deg[i] = 0; g_cur[i] = 0; }
}
__global__ void k_count(const int* __restrict__ dst, int e) {
    int i = blockIdx.x * blockDim.x + threadIdx.x;
    if (i < e) atomicAdd(&g_deg[dst[i]], 1);
}
__global__ void k_dinv(int n) {
    int i = blockIdx.x * blockDim.x + threadIdx.x;
    if (i < n) g_dinv[i] = rsqrtf((float)(g_deg[i] + 1));
}

// ---- exclusive scan of g_deg into g_off (3-kernel classic) ----
__global__ void k_bsum(int n) {
    __shared__ int sh[SCHUNK];
    int i = blockIdx.x * SCHUNK + threadIdx.x;
    sh[threadIdx.x] = (i < n) ? g_deg[i] : 0;
    __syncthreads();
    for (int off = SCHUNK / 2; off > 0; off >>= 1) {
        if (threadIdx.x < off) sh[threadIdx.x] += sh[threadIdx.x + off];
        __syncthreads();
    }
    if (threadIdx.x == 0) g_bsum[blockIdx.x] = sh[0];
}
__global__ void k_bscan(int nb) {
    __shared__ int sh[128];
    int v = (threadIdx.x < nb) ? g_bsum[threadIdx.x] : 0;
    sh[threadIdx.x] = v;
    __syncthreads();
    for (int off = 1; off < 128; off <<= 1) {
        int t = (threadIdx.x >= off) ? sh[threadIdx.x - off] : 0;
        __syncthreads();
        sh[threadIdx.x] += t;
        __syncthreads();
    }
    if (threadIdx.x < nb) g_bsum[threadIdx.x] = sh[threadIdx.x] - v;  // exclusive
}
__global__ void k_offsets(int n) {
    __shared__ int sh[SCHUNK];
    int i = blockIdx.x * SCHUNK + threadIdx.x;
    int v = (i < n) ? g_deg[i] : 0;
    sh[threadIdx.x] = v;
    __syncthreads();
    for (int off = 1; off < SCHUNK; off <<= 1) {
        int t = (threadIdx.x >= off) ? sh[threadIdx.x - off] : 0;
        __syncthreads();
        sh[threadIdx.x] += t;
        __syncthreads();
    }
    int excl = g_bsum[blockIdx.x] + sh[threadIdx.x] - v;
    if (i < n) g_off[i] = excl;
    if (i == n - 1) g_off[n] = excl + v;
}
__global__ void k_fill(const int* __restrict__ src, const int* __restrict__ dst, int e) {
    int i = blockIdx.x * blockDim.x + threadIdx.x;
    if (i < e) {
        int d = dst[i];
        int pos = g_off[d] + atomicAdd(&g_cur[d], 1);
        g_csr[pos] = src[i];
    }
}

// transpose + bf16-split ALL weights in one launch: slot = i / WSLOT
__global__ void k_convW_all(const float* __restrict__ W0, const float* __restrict__ W1,
                            const float* __restrict__ W2, const float* __restrict__ W3,
                            const float* __restrict__ Wm1, const float* __restrict__ Wm2) {
    int i = blockIdx.x * blockDim.x + threadIdx.x;
    if (i >= WTOT) return;
    int slot = i >> 14;
    int j = i & 16383;
    const float* W;
    int N;
    switch (slot) {
        case 0:  W = W0;  N = 128; break;
        case 1:  W = W1;  N = 128; break;
        case 2:  W = W2;  N = 128; break;
        case 3:  W = W3;  N = 128; break;
        case 4:  W = Wm1; N = 128; break;
        default: W = Wm2; N = 64;  break;
    }
    const int K = 128;
    int nrow = j / K;
    int k = j % K;
    float v = W[k * N + nrow];
    __nv_bfloat16 h = __float2bfloat16_rn(v);
    g_Wh[i] = h;
    g_Wl[i] = __float2bfloat16_rn(v - __bfloat162float(h));
}

// ---------------- HMMA GEMM body --------------------------------------------
// via split-bf16 (3 products, fp32 accum). Input A is fp32 (A32) or fp16 (A16).
// act = relu(a + abias) if abias.
// If C16 != 0:  C16[row] = half(acc * dinv[row])           (GCN layer mode)
// else:         C[row]  = acc + cbias (if cbias)           (MLP mode)
template <int BN>
__device__ __forceinline__ void gemm_body(const float* __restrict__ A32,
                                          const __half* __restrict__ A16,
                                          const float* __restrict__ abias,
                                          const __nv_bfloat16* __restrict__ Wh,
                                          const __nv_bfloat16* __restrict__ Wl,
                                          const float* __restrict__ cbias,
                                          float* __restrict__ C,
                                          __half* __restrict__ C16,
                                          int n, char* smem)
{
    constexpr int NT = BN / 16;            // n-tiles (8 cols each) per warp
    const unsigned int A_HI = 0;
    const unsigned int A_LO = 128 * PADB;
    const unsigned int B_HI = 2 * 128 * PADB;
    const unsigned int B_LO = B_HI + BN * PADB;

    const int tid  = threadIdx.x;
    const int wid  = tid >> 5;
    const int lane = tid & 31;
    const int wr   = wid >> 1;             // warp row group 0..3 (32 rows each)
    const int wc   = wid & 1;              // warp col group 0..1 (NT*8 cols each)
    const int row0 = blockIdx.x * 128;

    // ---- convert A tile (128 x 128 -> bf16 hi/lo), fused relu(+abias)
    for (int i = tid; i < 128 * 16; i += 256) {
        int row = i >> 4;
        int unit = i & 15;
        int grow = row0 + row;
        float v[8];
#pragma unroll
        for (int j = 0; j < 8; j++) v[j] = 0.f;
        if (grow < n) {
            if (A16) {
                uint4 u = *(const uint4*)(A16 + (size_t)grow * 128 + unit * 8);
                const __half2* hp = (const __half2*)&u;
#pragma unroll
                for (int j = 0; j < 4; j++) {
                    float2 f = __half22float2(hp[j]);
                    v[2 * j] = f.x; v[2 * j + 1] = f.y;
                }
            } else {
                const float4* p = (const float4*)(A32 + (size_t)grow * 128 + unit * 8);
                float4 a0 = p[0], a1 = p[1];
                v[0] = a0.x; v[1] = a0.y; v[2] = a0.z; v[3] = a0.w;
                v[4] = a1.x; v[5] = a1.y; v[6] = a1.z; v[7] = a1.w;
            }
        }
        if (abias) {
            const float4* b = (const float4*)(abias + unit * 8);
            float4 b0 = b[0], b1 = b[1];
            v[0] = fmaxf(v[0] + b0.x, 0.f); v[1] = fmaxf(v[1] + b0.y, 0.f);
            v[2] = fmaxf(v[2] + b0.z, 0.f); v[3] = fmaxf(v[3] + b0.w, 0.f);
            v[4] = fmaxf(v[4] + b1.x, 0.f); v[5] = fmaxf(v[5] + b1.y, 0.f);
            v[6] = fmaxf(v[6] + b1.z, 0.f); v[7] = fmaxf(v[7] + b1.w, 0.f);
        }
        unsigned int hi[4], lo[4];
#pragma unroll
        for (int j = 0; j < 4; j++) {
            __nv_bfloat16 h0 = __float2bfloat16_rn(v[2 * j]);
            __nv_bfloat16 h1 = __float2bfloat16_rn(v[2 * j + 1]);
            float r0 = v[2 * j] - __bfloat162float(h0);
            float r1 = v[2 * j + 1] - __bfloat162float(h1);
            __nv_bfloat16 l0 = __float2bfloat16_rn(r0);
            __nv_bfloat16 l1 = __float2bfloat16_rn(r1);
            hi[j] = ((unsigned int)__bfloat16_as_ushort(h1) << 16) | __bfloat16_as_ushort(h0);
            lo[j] = ((unsigned int)__bfloat16_as_ushort(l1) << 16) | __bfloat16_as_ushort(l0);
        }
        unsigned int off = (unsigned int)row * PADB + (unsigned int)unit * 16;
        *(uint4*)(smem + A_HI + off) = make_uint4(hi[0], hi[1], hi[2], hi[3]);
        *(uint4*)(smem + A_LO + off) = make_uint4(lo[0], lo[1], lo[2], lo[3]);
    }

    // ---- load W tiles (BN rows x 128 bf16 each, pre-split in global [N][K])
    for (int i = tid; i < BN * 16; i += 256) {
        int row = i >> 4;
        int unit = i & 15;
        unsigned int off = (unsigned int)row * PADB + (unsigned int)unit * 16;
        *(uint4*)(smem + B_HI + off) = ((const uint4*)Wh)[row * 16 + unit];
        *(uint4*)(smem + B_LO + off) = ((const uint4*)Wl)[row * 16 + unit];
    }
    __syncthreads();

    // ---- mainloop: 8 k-steps of m16n8k16, 3 products each
    const int g  = lane >> 2;
    const int tg = lane & 3;
    float acc[2][NT][4];
#pragma unroll
    for (int mt = 0; mt < 2; mt++)
#pragma unroll
        for (int nt = 0; nt < NT; nt++)
#pragma unroll
            for (int j = 0; j < 4; j++) acc[mt][nt][j] = 0.f;

#pragma unroll
    for (int ks = 0; ks < 8; ks++) {
        const unsigned int kb = (unsigned int)(ks * 16 + tg * 2) * 2;
        unsigned int ah[2][4], al[2][4];
#pragma unroll
        for (int mt = 0; mt < 2; mt++) {
            unsigned int ro = (unsigned int)(wr * 32 + mt * 16 + g) * PADB + kb;
            ah[mt][0] = *(const unsigned int*)(smem + A_HI + ro);
            ah[mt][1] = *(const unsigned int*)(smem + A_HI + ro + 8 * PADB);
            ah[mt][2] = *(const unsigned int*)(smem + A_HI + ro + 16);
            ah[mt][3] = *(const unsigned int*)(smem + A_HI + ro + 8 * PADB + 16);
            al[mt][0] = *(const unsigned int*)(smem + A_LO + ro);
            al[mt][1] = *(const unsigned int*)(smem + A_LO + ro + 8 * PADB);
            al[mt][2] = *(const unsigned int*)(smem + A_LO + ro + 16);
            al[mt][3] = *(const unsigned int*)(smem + A_LO + ro + 8 * PADB + 16);
        }
#pragma unroll
        for (int nt = 0; nt < NT; nt++) {
            unsigned int no = (unsigned int)(wc * NT * 8 + nt * 8 + g) * PADB + kb;
            unsigned int bh[2], bl[2];
            bh[0] = *(const unsigned int*)(smem + B_HI + no);
            bh[1] = *(const unsigned int*)(smem + B_HI + no + 16);
            bl[0] = *(const unsigned int*)(smem + B_LO + no);
            bl[1] = *(const unsigned int*)(smem + B_LO + no + 16);
#pragma unroll
            for (int mt = 0; mt < 2; mt++) {
                mma_bf16(acc[mt][nt], ah[mt], bh);
                mma_bf16(acc[mt][nt], ah[mt], bl);
                mma_bf16(acc[mt][nt], al[mt], bh);
            }
        }
    }

    // ---- epilogue
#pragma unroll
    for (int mt = 0; mt < 2; mt++) {
        int r0i = row0 + wr * 32 + mt * 16 + g;
        float s0 = 1.f, s1 = 1.f;
        if (C16) {
            if (r0i < n)     s0 = g_dinv[r0i];
            if (r0i + 8 < n) s1 = g_dinv[r0i + 8];
        }
#pragma unroll
        for (int nt = 0; nt < NT; nt++) {
            int col = wc * NT * 8 + nt * 8 + tg * 2;
            float c0 = acc[mt][nt][0], c1 = acc[mt][nt][1];
            float c2 = acc[mt][nt][2], c3 = acc[mt][nt][3];
            if (C16) {
                if (r0i < n)
                    *(__half2*)(C16 + (size_t)r0i * BN + col) =
                        __floats2half2_rn(c0 * s0, c1 * s0);
                if (r0i + 8 < n)
                    *(__half2*)(C16 + (size_t)(r0i + 8) * BN + col) =
                        __floats2half2_rn(c2 * s1, c3 * s1);
            } else {
                if (cbias) {
                    float b0 = cbias[col], b1 = cbias[col + 1];
                    c0 += b0; c1 += b1; c2 += b0; c3 += b1;
                }
                if (r0i < n)
                    *(float2*)(C + (size_t)r0i * BN + col) = make_float2(c0, c1);
                if (r0i + 8 < n)
                    *(float2*)(C + (size_t)(r0i + 8) * BN + col) = make_float2(c2, c3);
            }
        }
    }
}

__global__ void __launch_bounds__(256, 1)
k_gemm128(const float* A32, const __half* A16, const float* abias,
          const __nv_bfloat16* Wh, const __nv_bfloat16* Wl,
          const float* cbias, float* C, __half* C16, int n)
{
    extern __shared__ __align__(16) char smem_dyn[];
    gemm_body<128>(A32, A16, abias, Wh, Wl, cbias, C, C16, n, smem_dyn);
}

__global__ void __launch_bounds__(256, 1)
k_gemm64(const float* A32, const __half* A16, const float* abias,
         const __nv_bfloat16* Wh, const __nv_bfloat16* Wl,
         const float* cbias, float* C, __half* C16, int n)
{
    extern __shared__ __align__(16) char smem_dyn[];
    gemm_body<64>(A32, A16, abias, Wh, Wl, cbias, C, C16, n, smem_dyn);
}

// ---------------- CSR pull-gather (fp16, 2 rows per load step) -------------
// H16[d] = half( dinv[d] * (T16[d] + sum_{s in N(d)} T16[s]) )
// 16 lanes cover one 256B row (uint4 each); lanes 0-15 = neighbor j,
// lanes 16-31 = neighbor j+1. fp32 accumulation, cross-half shfl reduce.
__device__ __forceinline__ void add8(float* a, uint4 u) {
    const __half2* h = (const __half2*)&u;
#pragma unroll
    for (int i = 0; i < 4; i++) {
        float2 f = __half22float2(h[i]);
        a[2 * i]     += f.x;
        a[2 * i + 1] += f.y;
    }
}

__launch_bounds__(256)
__global__ void k_gather(const uint4* __restrict__ T16,   // row = 16 uint4
                         uint4* __restrict__ H16, int n)
{
    int warp = (blockIdx.x * blockDim.x + threadIdx.x) >> 5;
    int lane = threadIdx.x & 31;
    if (warp >= n) return;
    int half = lane >> 4;
    int sub  = lane & 15;
    int beg = g_off[warp];
    int total = g_off[warp + 1] - beg + 1;   // +1 self loop (virtual idx 0)

    float acc[8];
#pragma unroll
    for (int k = 0; k < 8; k++) acc[k] = 0.f;

    for (int base = 0; base < total; base += 32) {
        int cnt = total - base;
        if (cnt > 32) cnt = 32;
        int vj = base + lane;
        int idx = 0;
        if (lane < cnt) idx = (vj == 0) ? warp : g_csr[beg + vj - 1];
        int k = 0;
        for (; k + 4 <= cnt; k += 4) {
            int s0 = __shfl_sync(0xFFFFFFFFu, idx, k + half);
            int s1 = __shfl_sync(0xFFFFFFFFu, idx, k + 2 + half);
            uint4 u0 = T16[(size_t)s0 * 16 + sub];
            uint4 u1 = T16[(size_t)s1 * 16 + sub];
            add8(acc, u0);
            add8(acc, u1);
        }
        if (k + 2 <= cnt) {
            int s = __shfl_sync(0xFFFFFFFFu, idx, k + half);
            uint4 u = T16[(size_t)s * 16 + sub];
            add8(acc, u);
            k += 2;
        }
        if (k < cnt) {
            int s = __shfl_sync(0xFFFFFFFFu, idx, k);
            if (half == 0) {
                uint4 u = T16[(size_t)s * 16 + sub];
                add8(acc, u);
            }
        }
    }

    // combine the two halves: lanes 0-15 accumulate lane+16's partial
#pragma unroll
    for (int k = 0; k < 8; k++)
        acc[k] += __shfl_down_sync(0xFFFFFFFFu, acc[k], 16);

    if (half == 0) {
        float di = g_dinv[warp];
        uint4 o;
        __half2* oh = (__half2*)&o;
#pragma unroll
        for (int i = 0; i < 4; i++)
            oh[i] = __floats2half2_rn(acc[2 * i] * di, acc[2 * i + 1] * di);
        H16[(size_t)warp * 16 + sub] = o;
    }
}

// ---------------- log_softmax over 64 cols, one warp per row ---------------
__launch_bounds__(256)
__global__ void k_logsoftmax(const float* __restrict__ X,
                             float* __restrict__ out, int n)
{
    int warp = (blockIdx.x * blockDim.x + threadIdx.x) >> 5;
    int lane = threadIdx.x & 31;
    if (warp >= n) return;
    const float* row = X + (size_t)warp * 64;
    float v0 = row[lane];
    float v1 = row[lane + 32];
    float m = fmaxf(v0, v1);
#pragma unroll
    for (int o = 16; o > 0; o >>= 1) m = fmaxf(m, __shfl_xor_sync(0xFFFFFFFFu, m, o));
    float s = expf(v0 - m) + expf(v1 - m);
#pragma unroll
    for (int o = 16; o > 0; o >>= 1) s += __shfl_xor_sync(0xFFFFFFFFu, s, o);
    float lg = m + logf(s);
    float* orow = out + (size_t)warp * 64;
    orow[lane]      = v0 - lg;
    orow[lane + 32] = v1 - lg;
}

// ---------------- host launcher ---------------------------------------------
extern "C" void kernel_launch(void* const* d_in, const int* in_sizes, int n_in,
                              void* d_out, int out_size)
{
    const float* x   = (const float*)d_in[0];
    const int*   ei  = (const int*)d_in[1];
    const float* W0  = (const float*)d_in[2];
    const float* b0  = (const float*)d_in[3];
    const float* W1  = (const float*)d_in[4];
    const float* b1  = (const float*)d_in[5];
    const float* W2  = (const float*)d_in[6];
    const float* b2  = (const float*)d_in[7];
    const float* W3  = (const float*)d_in[8];
    const float* b3  = (const float*)d_in[9];
    const float* Wm1 = (const float*)d_in[10];
    const float* bm1 = (const float*)d_in[11];
    const float* Wm2 = (const float*)d_in[12];
    const float* bm2 = (const float*)d_in[13];
    float* out = (float*)d_out;

    const int n = in_sizes[0] / DIM;      // 100000
    const int e = in_sizes[1] / 2;        // 1600000
    const int* src = ei;
    const int* dst = ei + e;

    float* T = 0;
    __half* T16 = 0;
    __half* H16 = 0;
    float* Cb = 0;
    __nv_bfloat16* Wh = 0;
    __nv_bfloat16* Wl = 0;
    cudaGetSymbolAddress((void**)&T,   g_T);
    cudaGetSymbolAddress((void**)&T16, g_T16);
    cudaGetSymbolAddress((void**)&H16, g_H16);
    cudaGetSymbolAddress((void**)&Cb,  g_C);
    cudaGetSymbolAddress((void**)&Wh,  g_Wh);
    cudaGetSymbolAddress((void**)&Wl,  g_Wl);

    const int SM128 = 2 * 128 * PADB + 2 * 128 * PADB;   // 139264
    const int SM64  = 2 * 128 * PADB + 2 * 64  * PADB;   // 104448
    cudaFuncSetAttribute(k_gemm128, cudaFuncAttributeMaxDynamicSharedMemorySize, SM128);
    cudaFuncSetAttribute(k_gemm64,  cudaFuncAttributeMaxDynamicSharedMemorySize, SM64);

    const int nscanb = (n + SCHUNK - 1) / SCHUNK;

    // ---- setup: degrees, dinv, CSR (offsets + fill), weight split ----
    k_zero<<<(n + 255) / 256, 256>>>(n);
    k_count<<<(e + 255) / 256, 256>>>(dst, e);
    k_dinv<<<(n + 255) / 256, 256>>>(n);
    k_bsum<<<nscanb, SCHUNK>>>(n);
    k_bscan<<<1, 128>>>(nscanb);
    k_offsets<<<nscanb, SCHUNK>>>(n);
    k_fill<<<(e + 255) / 256, 256>>>(src, dst, e);
    k_convW_all<<<(WTOT + 255) / 256, 256>>>(W0, W1, W2, W3, Wm1, Wm2);

    const int gblocks = (n + 127) / 128;                 // 782
    const int gatherb = (n * 32 + 255) / 256;            // 12500

    // ---- 4 GCN layers: T16 = (act(H)@W) * dinv (fp16) ; H16 = gather(T16) ----
    k_gemm128<<<gblocks, 256, SM128>>>(x, 0, 0, Wh + 0 * WSLOT, Wl + 0 * WSLOT, 0, 0, T16, n);
    k_gather<<<gatherb, 256>>>((const uint4*)T16, (uint4*)H16, n);

    k_gemm128<<<gblocks, 256, SM128>>>(0, H16, b0, Wh + 1 * WSLOT, Wl + 1 * WSLOT, 0, 0, T16, n);
    k_gather<<<gatherb, 256>>>((const uint4*)T16, (uint4*)H16, n);

    k_gemm128<<<gblocks, 256, SM128>>>(0, H16, b1, Wh + 2 * WSLOT, Wl + 2 * WSLOT, 0, 0, T16, n);
    k_gather<<<gatherb, 256>>>((const uint4*)T16, (uint4*)H16, n);

    k_gemm128<<<gblocks, 256, SM128>>>(0, H16, b2, Wh + 3 * WSLOT, Wl + 3 * WSLOT, 0, 0, T16, n);
    k_gather<<<gatherb, 256>>>((const uint4*)T16, (uint4*)H16, n);

    // ---- MLP head (fp32 output path) ----
    k_gemm128<<<gblocks, 256, SM128>>>(0, H16, b3, Wh + 4 * WSLOT, Wl + 4 * WSLOT, bm1, T, 0, n);
    k_gemm64<<<gblocks, 256, SM64>>>(T, 0, 0, Wh + 5 * WSLOT, Wl + 5 * WSLOT, bm2, Cb, 0, n);

    // ---- log_softmax -> out ----
    k_logsoftmax<<<(n * 32 + 255) / 256, 256>>>(Cb, out, n);
}

// round 9
// speedup vs baseline: 2.4781x; 1.2099x over previous
#include <cuda_runtime.h>
#include <cuda_fp16.h>
#include <cstdint>
#include <stdint.h>
#include <math.h>

// Problem constants (fixed by the dataset)
#define N_NODES 100000
#define N_EDGES 1600000
#define DIM 128
#define ODIM 64
#define WSLOT 16384
#define WTOT (5 * WSLOT + ODIM * DIM)
#define PADB 272   // smem row stride in bytes, multiple of 16, conflict-free
#define SCHUNK 1024

// ---------------- scratch (static device globals; no allocation) -----------
__device__ float       g_T[(size_t)N_NODES * DIM];   // fp32 MLP intermediate
__device__ signed char g_M8[(size_t)N_NODES * DIM];  // int8 messages (GCN layers)
__device__ float       g_sc[N_NODES];                // per-row dequant scale
__device__ __half      g_H16[(size_t)N_NODES * DIM]; // fp16 aggregated features
__device__ float       g_C[(size_t)N_NODES * ODIM];  // final pre-softmax logits
__device__ int         g_deg[N_NODES];
__device__ int         g_cur[N_NODES];
__device__ int         g_off[N_NODES + 1];
__device__ int         g_csr[N_EDGES];
__device__ int         g_bsum[128];
__device__ float       g_dinv[N_NODES];
__device__ __half      g_Wf[WTOT];                   // fp16 transposed weights [N][K]

// ---------------- mma.sync fp16 helper (baseline PTX) ----------------------
__device__ __forceinline__ void mma_f16(float* c, const unsigned int* a,
                                        const unsigned int* b) {
    asm volatile(
        "mma.sync.aligned.m16n8k16.row.col.f32.f16.f16.f32 "
        "{%0,%1,%2,%3}, {%4,%5,%6,%7}, {%8,%9}, {%0,%1,%2,%3};"
        : "+f"(c[0]), "+f"(c[1]), "+f"(c[2]), "+f"(c[3])
        : "r"(a[0]), "r"(a[1]), "r"(a[2]), "r"(a[3]), "r"(b[0]), "r"(b[1]));
}

// ---------------- setup kernels --------------------------------------------
__global__ void k_zero(int n) {
    int i = blockIdx.x * blockDim.x + threadIdx.x;
    if (i < n) { g_deg[i] = 0; g_cur[i] = 0; }
}
__global__ void k_count(const int* __restrict__ dst, int e) {
    int i = blockIdx.x * blockDim.x + threadIdx.x;
    if (i < e) atomicAdd(&g_deg[dst[i]], 1);
}
__global__ void k_dinv(int n) {
    int i = blockIdx.x * blockDim.x + threadIdx.x;
    if (i < n) g_dinv[i] = rsqrtf((float)(g_deg[i] + 1));
}

// ---- exclusive scan of g_deg into g_off ----
__global__ void k_bsum(int n) {
    __shared__ int sh[SCHUNK];
    int i = blockIdx.x * SCHUNK + threadIdx.x;
    sh[threadIdx.x] = (i < n) ? g_deg[i] : 0;
    __syncthreads();
    for (int off = SCHUNK / 2; off > 0; off >>= 1) {
        if (threadIdx.x < off) sh[threadIdx.x] += sh[threadIdx.x + off];
        __syncthreads();
    }
    if (threadIdx.x == 0) g_bsum[blockIdx.x] = sh[0];
}
__global__ void k_bscan(int nb) {
    __shared__ int sh[128];
    int v = (threadIdx.x < nb) ? g_bsum[threadIdx.x] : 0;
    sh[threadIdx.x] = v;
    __syncthreads();
    for (int off = 1; off < 128; off <<= 1) {
        int t = (threadIdx.x >= off) ? sh[threadIdx.x - off] : 0;
        __syncthreads();
        sh[threadIdx.x] += t;
        __syncthreads();
    }
    if (threadIdx.x < nb) g_bsum[threadIdx.x] = sh[threadIdx.x] - v;
}
__global__ void k_offsets(int n) {
    __shared__ int sh[SCHUNK];
    int i = blockIdx.x * SCHUNK + threadIdx.x;
    int v = (i < n) ? g_deg[i] : 0;
    sh[threadIdx.x] = v;
    __syncthreads();
    for (int off = 1; off < SCHUNK; off <<= 1) {
        int t = (threadIdx.x >= off) ? sh[threadIdx.x - off] : 0;
        __syncthreads();
        sh[threadIdx.x] += t;
        __syncthreads();
    }
    int excl = g_bsum[blockIdx.x] + sh[threadIdx.x] - v;
    if (i < n) g_off[i] = excl;
    if (i == n - 1) g_off[n] = excl + v;
}
__global__ void k_fill(const int* __restrict__ src, const int* __restrict__ dst, int e) {
    int i = blockIdx.x * blockDim.x + threadIdx.x;
    if (i < e) {
        int d = dst[i];
        int pos = g_off[d] + atomicAdd(&g_cur[d], 1);
        g_csr[pos] = src[i];
    }
}

// transpose + fp16 convert ALL weights in one launch
__global__ void k_convW_all(const float* __restrict__ W0, const float* __restrict__ W1,
                            const float* __restrict__ W2, const float* __restrict__ W3,
                            const float* __restrict__ Wm1, const float* __restrict__ Wm2) {
    int i = blockIdx.x * blockDim.x + threadIdx.x;
    if (i >= WTOT) return;
    int slot = i >> 14;
    int j = i & 16383;
    const float* W;
    int N;
    switch (slot) {
        case 0:  W = W0;  N = 128; break;
        case 1:  W = W1;  N = 128; break;
        case 2:  W = W2;  N = 128; break;
        case 3:  W = W3;  N = 128; break;
        case 4:  W = Wm1; N = 128; break;
        default: W = Wm2; N = 64;  break;
    }
    const int K = 128;
    int nrow = j / K;
    int k = j % K;
    g_Wf[i] = __float2half_rn(W[k * N + nrow]);
}

// ---------------- fp16 HMMA GEMM body ----------------------------------------
// acc = act(A) @ W, single fp16 product, fp32 accum. act = relu(a+abias) if abias.
// If C8 != 0 (GCN mode): per-row absmax M -> int8 quantize, g_sc[row]=M*dinv/127.
// Else (MLP mode): C[row] = acc + cbias.
template <int BN>
__device__ __forceinline__ void gemm_body(const float* __restrict__ A32,
                                          const __half* __restrict__ A16,
                                          const float* __restrict__ abias,
                                          const __half* __restrict__ Wf,
                                          const float* __restrict__ cbias,
                                          float* __restrict__ C,
                                          signed char* __restrict__ C8,
                                          float* __restrict__ Csc,
                                          int n, char* smem)
{
    constexpr int NT = BN / 16;
    const unsigned int A_OF = 0;
    const unsigned int B_OF = 128 * PADB;

    const int tid  = threadIdx.x;
    const int wid  = tid >> 5;
    const int lane = tid & 31;
    const int wr   = wid >> 1;
    const int wc   = wid & 1;
    const int row0 = blockIdx.x * 128;

    // ---- A tile -> fp16 smem (row = 256B data in PADB stride), fused relu(+abias)
    for (int i = tid; i < 128 * 16; i += 256) {
        int row = i >> 4;
        int unit = i & 15;
        int grow = row0 + row;
        uint4 u = make_uint4(0, 0, 0, 0);
        __half2* hp = (__half2*)&u;
        if (grow < n) {
            if (A16) {
                u = *(const uint4*)(A16 + (size_t)grow * 128 + unit * 8);
            } else {
                const float4* p = (const float4*)(A32 + (size_t)grow * 128 + unit * 8);
                float4 a0 = p[0], a1 = p[1];
                hp[0] = __floats2half2_rn(a0.x, a0.y);
                hp[1] = __floats2half2_rn(a0.z, a0.w);
                hp[2] = __floats2half2_rn(a1.x, a1.y);
                hp[3] = __floats2half2_rn(a1.z, a1.w);
            }
        }
        if (abias) {
            const float4* b = (const float4*)(abias + unit * 8);
            float4 b0 = b[0], b1 = b[1];
            float bb[8];
            bb[0] = b0.x; bb[1] = b0.y; bb[2] = b0.z; bb[3] = b0.w;
            bb[4] = b1.x; bb[5] = b1.y; bb[6] = b1.z; bb[7] = b1.w;
#pragma unroll
            for (int j = 0; j < 4; j++) {
                float2 f = __half22float2(hp[j]);
                f.x = fmaxf(f.x + bb[2 * j], 0.f);
                f.y = fmaxf(f.y + bb[2 * j + 1], 0.f);
                hp[j] = __floats2half2_rn(f.x, f.y);
            }
        }
        *(uint4*)(smem + A_OF + (unsigned int)row * PADB + (unsigned int)unit * 16) = u;
    }

    // ---- W tile (BN rows x 128 fp16, [N][K])
    for (int i = tid; i < BN * 16; i += 256) {
        int row = i >> 4;
        int unit = i & 15;
        *(uint4*)(smem + B_OF + (unsigned int)row * PADB + (unsigned int)unit * 16) =
            ((const uint4*)Wf)[row * 16 + unit];
    }
    __syncthreads();

    // ---- mainloop: 8 k-steps of m16n8k16, single product
    const int g  = lane >> 2;
    const int tg = lane & 3;
    float acc[2][NT][4];
#pragma unroll
    for (int mt = 0; mt < 2; mt++)
#pragma unroll
        for (int nt = 0; nt < NT; nt++)
#pragma unroll
            for (int j = 0; j < 4; j++) acc[mt][nt][j] = 0.f;

#pragma unroll
    for (int ks = 0; ks < 8; ks++) {
        const unsigned int kb = (unsigned int)(ks * 16 + tg * 2) * 2;
        unsigned int a[2][4];
#pragma unroll
        for (int mt = 0; mt < 2; mt++) {
            unsigned int ro = A_OF + (unsigned int)(wr * 32 + mt * 16 + g) * PADB + kb;
            a[mt][0] = *(const unsigned int*)(smem + ro);
            a[mt][1] = *(const unsigned int*)(smem + ro + 8 * PADB);
            a[mt][2] = *(const unsigned int*)(smem + ro + 16);
            a[mt][3] = *(const unsigned int*)(smem + ro + 8 * PADB + 16);
        }
#pragma unroll
        for (int nt = 0; nt < NT; nt++) {
            unsigned int no = B_OF + (unsigned int)(wc * NT * 8 + nt * 8 + g) * PADB + kb;
            unsigned int b[2];
            b[0] = *(const unsigned int*)(smem + no);
            b[1] = *(const unsigned int*)(smem + no + 16);
#pragma unroll
            for (int mt = 0; mt < 2; mt++)
                mma_f16(acc[mt][nt], a[mt], b);
        }
    }

    // ---- epilogue
    if (C8) {
        // per-row absmax via smem
        __syncthreads();
        float* rmax = (float*)smem;
        if (tid < 128) rmax[tid] = 0.f;
        __syncthreads();
#pragma unroll
        for (int mt = 0; mt < 2; mt++) {
            int lr = wr * 32 + mt * 16 + g;
            float m0 = 0.f, m1 = 0.f;
#pragma unroll
            for (int nt = 0; nt < NT; nt++) {
                m0 = fmaxf(m0, fmaxf(fabsf(acc[mt][nt][0]), fabsf(acc[mt][nt][1])));
                m1 = fmaxf(m1, fmaxf(fabsf(acc[mt][nt][2]), fabsf(acc[mt][nt][3])));
            }
            atomicMax((int*)&rmax[lr], __float_as_int(m0));
            atomicMax((int*)&rmax[lr + 8], __float_as_int(m1));
        }
        __syncthreads();
#pragma unroll
        for (int mt = 0; mt < 2; mt++) {
            int lr = wr * 32 + mt * 16 + g;
            int grow = row0 + lr;
            float M0 = rmax[lr], M1 = rmax[lr + 8];
            float q0 = (M0 > 0.f) ? 127.f / M0 : 0.f;
            float q1 = (M1 > 0.f) ? 127.f / M1 : 0.f;
            if (wc == 0 && tg == 0) {   // one thread per row writes scale
                if (grow < n)     Csc[grow]     = M0 * g_dinv[grow] * (1.f / 127.f);
                if (grow + 8 < n) Csc[grow + 8] = M1 * g_dinv[grow + 8] * (1.f / 127.f);
            }
#pragma unroll
            for (int nt = 0; nt < NT; nt++) {
                int col = wc * NT * 8 + nt * 8 + tg * 2;
                if (grow < n) {
                    int b0 = __float2int_rn(acc[mt][nt][0] * q0);
                    int b1 = __float2int_rn(acc[mt][nt][1] * q0);
                    unsigned short us = (unsigned short)(((b1 & 0xff) << 8) | (b0 & 0xff));
                    *(unsigned short*)(C8 + (size_t)grow * 128 + col) = us;
                }
                if (grow + 8 < n) {
                    int b2 = __float2int_rn(acc[mt][nt][2] * q1);
                    int b3 = __float2int_rn(acc[mt][nt][3] * q1);
                    unsigned short us = (unsigned short)(((b3 & 0xff) << 8) | (b2 & 0xff));
                    *(unsigned short*)(C8 + (size_t)(grow + 8) * 128 + col) = us;
                }
            }
        }
    } else {
#pragma unroll
        for (int mt = 0; mt < 2; mt++) {
            int r0i = row0 + wr * 32 + mt * 16 + g;
#pragma unroll
            for (int nt = 0; nt < NT; nt++) {
                int col = wc * NT * 8 + nt * 8 + tg * 2;
                float c0 = acc[mt][nt][0], c1 = acc[mt][nt][1];
                float c2 = acc[mt][nt][2], c3 = acc[mt][nt][3];
                if (cbias) {
                    float b0 = cbias[col], b1 = cbias[col + 1];
                    c0 += b0; c1 += b1; c2 += b0; c3 += b1;
                }
                if (r0i < n)
                    *(float2*)(C + (size_t)r0i * BN + col) = make_float2(c0, c1);
                if (r0i + 8 < n)
                    *(float2*)(C + (size_t)(r0i + 8) * BN + col) = make_float2(c2, c3);
            }
        }
    }
}

__global__ void __launch_bounds__(256, 2)
k_gemm128(const float* A32, const __half* A16, const float* abias,
          const __half* Wf, const float* cbias,
          float* C, signed char* C8, float* Csc, int n)
{
    extern __shared__ __align__(16) char smem_dyn[];
    gemm_body<128>(A32, A16, abias, Wf, cbias, C, C8, Csc, n, smem_dyn);
}

__global__ void __launch_bounds__(256, 2)
k_gemm64(const float* A32, const __half* A16, const float* abias,
         const __half* Wf, const float* cbias,
         float* C, signed char* C8, float* Csc, int n)
{
    extern __shared__ __align__(16) char smem_dyn[];
    gemm_body<64>(A32, A16, abias, Wf, cbias, C, C8, Csc, n, smem_dyn);
}

// ---------------- CSR pull-gather (int8 rows + per-row scale) --------------
// H16[d] = half( dinv[d] * sum_{s in N(d) U {d}} sc[s] * M8[s] )
// Row = 128 int8 = 128B; 16 lanes x uint2. Lanes 0-15 neighbor j, 16-31 j+1.
__device__ __forceinline__ void addq(float* a, uint2 u, float sc) {
    a[0] += sc * (float)(signed char)(u.x);
    a[1] += sc * (float)(signed char)(u.x >> 8);
    a[2] += sc * (float)(signed char)(u.x >> 16);
    a[3] += sc * (float)(signed char)(u.x >> 24);
    a[4] += sc * (float)(signed char)(u.y);
    a[5] += sc * (float)(signed char)(u.y >> 8);
    a[6] += sc * (float)(signed char)(u.y >> 16);
    a[7] += sc * (float)(signed char)(u.y >> 24);
}

__launch_bounds__(256)
__global__ void k_gather(const uint2* __restrict__ M8,   // row = 16 uint2
                         const float* __restrict__ sc,
                         uint4* __restrict__ H16, int n)
{
    int warp = (blockIdx.x * blockDim.x + threadIdx.x) >> 5;
    int lane = threadIdx.x & 31;
    if (warp >= n) return;
    int half = lane >> 4;
    int sub  = lane & 15;
    int beg = g_off[warp];
    int total = g_off[warp + 1] - beg + 1;   // +1 self loop (virtual idx 0)

    float acc[8];
#pragma unroll
    for (int k = 0; k < 8; k++) acc[k] = 0.f;

    for (int base = 0; base < total; base += 32) {
        int cnt = total - base;
        if (cnt > 32) cnt = 32;
        int vj = base + lane;
        int idx = 0;
        if (lane < cnt) idx = (vj == 0) ? warp : g_csr[beg + vj - 1];
        int k = 0;
        for (; k + 4 <= cnt; k += 4) {
            int s0 = __shfl_sync(0xFFFFFFFFu, idx, k + half);
            int s1 = __shfl_sync(0xFFFFFFFFu, idx, k + 2 + half);
            uint2 u0 = M8[(size_t)s0 * 16 + sub];
            float f0 = sc[s0];
            uint2 u1 = M8[(size_t)s1 * 16 + sub];
            float f1 = sc[s1];
            addq(acc, u0, f0);
            addq(acc, u1, f1);
        }
        if (k + 2 <= cnt) {
            int s = __shfl_sync(0xFFFFFFFFu, idx, k + half);
            uint2 u = M8[(size_t)s * 16 + sub];
            addq(acc, u, sc[s]);
            k += 2;
        }
        if (k < cnt) {
            int s = __shfl_sync(0xFFFFFFFFu, idx, k);
            if (half == 0) {
                uint2 u = M8[(size_t)s * 16 + sub];
                addq(acc, u, sc[s]);
            }
        }
    }

#pragma unroll
    for (int k = 0; k < 8; k++)
        acc[k] += __shfl_down_sync(0xFFFFFFFFu, acc[k], 16);

    if (half == 0) {
        float di = g_dinv[warp];
        uint4 o;
        __half2* oh = (__half2*)&o;
#pragma unroll
        for (int i = 0; i < 4; i++)
            oh[i] = __floats2half2_rn(acc[2 * i] * di, acc[2 * i + 1] * di);
        H16[(size_t)warp * 16 + sub] = o;
    }
}

// ---------------- log_softmax over 64 cols, one warp per row ---------------
__launch_bounds__(256)
__global__ void k_logsoftmax(const float* __restrict__ X,
                             float* __restrict__ out, int n)
{
    int warp = (blockIdx.x * blockDim.x + threadIdx.x) >> 5;
    int lane = threadIdx.x & 31;
    if (warp >= n) return;
    const float* row = X + (size_t)warp * 64;
    float v0 = row[lane];
    float v1 = row[lane + 32];
    float m = fmaxf(v0, v1);
#pragma unroll
    for (int o = 16; o > 0; o >>= 1) m = fmaxf(m, __shfl_xor_sync(0xFFFFFFFFu, m, o));
    float s = expf(v0 - m) + expf(v1 - m);
#pragma unroll
    for (int o = 16; o > 0; o >>= 1) s += __shfl_xor_sync(0xFFFFFFFFu, s, o);
    float lg = m + logf(s);
    float* orow = out + (size_t)warp * 64;
    orow[lane]      = v0 - lg;
    orow[lane + 32] = v1 - lg;
}

// ---------------- host launcher ---------------------------------------------
extern "C" void kernel_launch(void* const* d_in, const int* in_sizes, int n_in,
                              void* d_out, int out_size)
{
    const float* x   = (const float*)d_in[0];
    const int*   ei  = (const int*)d_in[1];
    const float* W0  = (const float*)d_in[2];
    const float* b0  = (const float*)d_in[3];
    const float* W1  = (const float*)d_in[4];
    const float* b1  = (const float*)d_in[5];
    const float* W2  = (const float*)d_in[6];
    const float* b2  = (const float*)d_in[7];
    const float* W3  = (const float*)d_in[8];
    const float* b3  = (const float*)d_in[9];
    const float* Wm1 = (const float*)d_in[10];
    const float* bm1 = (const float*)d_in[11];
    const float* Wm2 = (const float*)d_in[12];
    const float* bm2 = (const float*)d_in[13];
    float* out = (float*)d_out;

    const int n = in_sizes[0] / DIM;      // 100000
    const int e = in_sizes[1] / 2;        // 1600000
    const int* src = ei;
    const int* dst = ei + e;

    float* T = 0;
    signed char* M8 = 0;
    float* Sc = 0;
    __half* H16 = 0;
    float* Cb = 0;
    __half* Wf = 0;
    cudaGetSymbolAddress((void**)&T,   g_T);
    cudaGetSymbolAddress((void**)&M8,  g_M8);
    cudaGetSymbolAddress((void**)&Sc,  g_sc);
    cudaGetSymbolAddress((void**)&H16, g_H16);
    cudaGetSymbolAddress((void**)&Cb,  g_C);
    cudaGetSymbolAddress((void**)&Wf,  g_Wf);

    const int SM128 = 128 * PADB + 128 * PADB;   // 69632
    const int SM64  = 128 * PADB + 64 * PADB;    // 52224
    cudaFuncSetAttribute(k_gemm128, cudaFuncAttributeMaxDynamicSharedMemorySize, SM128);
    cudaFuncSetAttribute(k_gemm64,  cudaFuncAttributeMaxDynamicSharedMemorySize, SM64);

    const int nscanb = (n + SCHUNK - 1) / SCHUNK;

    // ---- setup: degrees, dinv, CSR (offsets + fill), weight convert ----
    k_zero<<<(n + 255) / 256, 256>>>(n);
    k_count<<<(e + 255) / 256, 256>>>(dst, e);
    k_dinv<<<(n + 255) / 256, 256>>>(n);
    k_bsum<<<nscanb, SCHUNK>>>(n);
    k_bscan<<<1, 128>>>(nscanb);
    k_offsets<<<nscanb, SCHUNK>>>(n);
    k_fill<<<(e + 255) / 256, 256>>>(src, dst, e);
    k_convW_all<<<(WTOT + 255) / 256, 256>>>(W0, W1, W2, W3, Wm1, Wm2);

    const int gblocks = (n + 127) / 128;                 // 782
    const int gatherb = (n * 32 + 255) / 256;            // 12500

    // ---- 4 GCN layers: M8/sc = quant((act(H)@W)); H16 = gather ----
    k_gemm128<<<gblocks, 256, SM128>>>(x, 0, 0, Wf + 0 * WSLOT, 0, 0, M8, Sc, n);
    k_gather<<<gatherb, 256>>>((const uint2*)M8, Sc, (uint4*)H16, n);

    k_gemm128<<<gblocks, 256, SM128>>>(0, H16, b0, Wf + 1 * WSLOT, 0, 0, M8, Sc, n);
    k_gather<<<gatherb, 256>>>((const uint2*)M8, Sc, (uint4*)H16, n);

    k_gemm128<<<gblocks, 256, SM128>>>(0, H16, b1, Wf + 2 * WSLOT, 0, 0, M8, Sc, n);
    k_gather<<<gatherb, 256>>>((const uint2*)M8, Sc, (uint4*)H16, n);

    k_gemm128<<<gblocks, 256, SM128>>>(0, H16, b2, Wf + 3 * WSLOT, 0, 0, M8, Sc, n);
    k_gather<<<gatherb, 256>>>((const uint2*)M8, Sc, (uint4*)H16, n);

    // ---- MLP head (fp32 output path) ----
    k_gemm128<<<gblocks, 256, SM128>>>(0, H16, b3, Wf + 4 * WSLOT, bm1, T, 0, 0, n);
    k_gemm64<<<gblocks, 256, SM64>>>(T, 0, 0, Wf + 5 * WSLOT, bm2, Cb, 0, 0, n);

    // ---- log_softmax -> out ----
    k_logsoftmax<<<(n * 32 + 255) / 256, 256>>>(Cb, out, n);
}